// round 4
// baseline (speedup 1.0000x reference)
#include <cuda_runtime.h>

#define B_      32
#define DIM_    256
#define N_      512
#define NHEADS  8
#define KDIM    16
#define NH_KD   128
#define DH_     512
#define HQKV    768
#define VDIM    64

typedef unsigned long long ull;

__device__ __forceinline__ ull dup2(float x) {
    ull r; asm("mov.b64 %0, {%1, %1};" : "=l"(r) : "f"(x)); return r;
}
__device__ __forceinline__ void ffma2(ull& d, ull a, ull b) {
    asm("fma.rn.f32x2 %0, %1, %2, %0;" : "+l"(d) : "l"(a), "l"(b));
}
__device__ __forceinline__ float2 unp(ull v) {
    float2 f; asm("mov.b64 {%0, %1}, %2;" : "=f"(f.x), "=f"(f.y) : "l"(v)); return f;
}

// Scratch (device globals: no allocation allowed)
__device__ float g_qkv[(size_t)B_ * HQKV * N_];   // [b][768][512]
__device__ float g_q  [(size_t)B_ * NH_KD * N_];  // dw-conv output
__device__ float g_att[(size_t)B_ * DH_ * N_];    // attention output (pre-relu)

// ---------------------------------------------------------------------------
// CBN GEMM: C[b] = A[M,K] @ B[b][K,N]; C = acc*scale[m]+bias[m]; opt. relu(B).
// 128x128 tile, BK=8, 256 threads, 8x8 micro-tile, fp32x2 packed FMA,
// double-buffered SMEM, compile-time K.
// ---------------------------------------------------------------------------
template <int K, bool RELU_B>
__global__ __launch_bounds__(256, 2)
void gemm_cbn(const float* __restrict__ A, const float* __restrict__ Bg,
              float* __restrict__ Cg, const float* __restrict__ scale,
              const float* __restrict__ bias, int M, int N)
{
    const int b = blockIdx.z;
    const float* Bb = Bg + (size_t)b * K * N;
    float* Cb = Cg + (size_t)b * M * N;
    const int m0 = blockIdx.y * 128;
    const int n0 = blockIdx.x * 128;
    const int tid = threadIdx.x;

    __shared__ float As[2][8][128];
    __shared__ float Bs[2][8][128];

    const int ty = tid >> 4, tx = tid & 15;
    const int ar = tid >> 1, ac = (tid & 1) * 4;
    const int br = tid >> 5, bc = (tid & 31) * 4;

    const float* Aptr = &A[(size_t)(m0 + ar) * K + ac];
    const float* Bptr = &Bb[(size_t)br * N + n0 + bc];

    ull acc2[2][2][8];
#pragma unroll
    for (int ih = 0; ih < 2; ih++)
#pragma unroll
        for (int i2 = 0; i2 < 2; i2++)
#pragma unroll
            for (int j = 0; j < 8; j++) acc2[ih][i2][j] = 0ULL;

    // prologue: tile 0 -> buffer 0
    {
        float4 a = *(const float4*)Aptr;
        As[0][ac + 0][ar] = a.x; As[0][ac + 1][ar] = a.y;
        As[0][ac + 2][ar] = a.z; As[0][ac + 3][ar] = a.w;
        float4 v = *(const float4*)Bptr;
        if (RELU_B) {
            v.x = fmaxf(v.x, 0.f); v.y = fmaxf(v.y, 0.f);
            v.z = fmaxf(v.z, 0.f); v.w = fmaxf(v.w, 0.f);
        }
        *(float4*)&Bs[0][br][bc] = v;
    }
    __syncthreads();

    constexpr int T = K / 8;
#pragma unroll 2
    for (int t = 0; t < T; t++) {
        const int cur = t & 1;
        float4 na, nb;
        if (t + 1 < T) {
            na = *(const float4*)(Aptr + (t + 1) * 8);
            nb = *(const float4*)(Bptr + (size_t)(t + 1) * 8 * N);
        }

#pragma unroll
        for (int kk = 0; kk < 8; kk++) {
            ull a2[2][2];
            {
                ulonglong2 t0 = *(const ulonglong2*)&As[cur][kk][ty * 4];
                a2[0][0] = t0.x; a2[0][1] = t0.y;
                ulonglong2 t1 = *(const ulonglong2*)&As[cur][kk][64 + ty * 4];
                a2[1][0] = t1.x; a2[1][1] = t1.y;
            }
            float4 bl = *(const float4*)&Bs[cur][kk][tx * 4];
            float4 bh = *(const float4*)&Bs[cur][kk][64 + tx * 4];
            ull bd[8];
            bd[0] = dup2(bl.x); bd[1] = dup2(bl.y);
            bd[2] = dup2(bl.z); bd[3] = dup2(bl.w);
            bd[4] = dup2(bh.x); bd[5] = dup2(bh.y);
            bd[6] = dup2(bh.z); bd[7] = dup2(bh.w);
#pragma unroll
            for (int ih = 0; ih < 2; ih++)
#pragma unroll
                for (int i2 = 0; i2 < 2; i2++)
#pragma unroll
                    for (int j = 0; j < 8; j++)
                        ffma2(acc2[ih][i2][j], a2[ih][i2], bd[j]);
        }

        if (t + 1 < T) {
            const int nxt = cur ^ 1;
            As[nxt][ac + 0][ar] = na.x; As[nxt][ac + 1][ar] = na.y;
            As[nxt][ac + 2][ar] = na.z; As[nxt][ac + 3][ar] = na.w;
            if (RELU_B) {
                nb.x = fmaxf(nb.x, 0.f); nb.y = fmaxf(nb.y, 0.f);
                nb.z = fmaxf(nb.z, 0.f); nb.w = fmaxf(nb.w, 0.f);
            }
            *(float4*)&Bs[nxt][br][bc] = nb;
        }
        __syncthreads();
    }

    // epilogue: unpack, scale/bias, store
#pragma unroll
    for (int ih = 0; ih < 2; ih++) {
#pragma unroll
        for (int i2 = 0; i2 < 2; i2++) {
            const int mA = m0 + ih * 64 + ty * 4 + 2 * i2;
            float fl[8], fh[8];
#pragma unroll
            for (int j = 0; j < 8; j++) {
                float2 f = unp(acc2[ih][i2][j]);
                fl[j] = f.x; fh[j] = f.y;
            }
            float sL = scale[mA],     bL = bias[mA];
            float sH = scale[mA + 1], bH = bias[mA + 1];
            float4 o;
            o.x = fmaf(fl[0], sL, bL); o.y = fmaf(fl[1], sL, bL);
            o.z = fmaf(fl[2], sL, bL); o.w = fmaf(fl[3], sL, bL);
            *(float4*)&Cb[(size_t)mA * N + n0 + tx * 4] = o;
            o.x = fmaf(fl[4], sL, bL); o.y = fmaf(fl[5], sL, bL);
            o.z = fmaf(fl[6], sL, bL); o.w = fmaf(fl[7], sL, bL);
            *(float4*)&Cb[(size_t)mA * N + n0 + 64 + tx * 4] = o;
            o.x = fmaf(fh[0], sH, bH); o.y = fmaf(fh[1], sH, bH);
            o.z = fmaf(fh[2], sH, bH); o.w = fmaf(fh[3], sH, bH);
            *(float4*)&Cb[(size_t)(mA + 1) * N + n0 + tx * 4] = o;
            o.x = fmaf(fh[4], sH, bH); o.y = fmaf(fh[5], sH, bH);
            o.z = fmaf(fh[6], sH, bH); o.w = fmaf(fh[7], sH, bH);
            *(float4*)&Cb[(size_t)(mA + 1) * N + n0 + 64 + tx * 4] = o;
        }
    }
}

// ---------------------------------------------------------------------------
// Depthwise 3x3x3 conv on q channels, pad=1, then scale/bias.
// ---------------------------------------------------------------------------
__global__ __launch_bounds__(256)
void dwconv_kernel(const float* __restrict__ w,
                   const float* __restrict__ scale,
                   const float* __restrict__ bias)
{
    int idx = blockIdx.x * 256 + threadIdx.x;     // B*128*512 threads
    int n = idx & 511;
    int c = (idx >> 9) & 127;
    int b = idx >> 16;
    int xx = n & 7, yy = (n >> 3) & 7, zz = n >> 6;

    const float* src = g_qkv + ((size_t)b * HQKV + c) * N_;
    const float* wc = w + c * 27;
    float acc = 0.f;
#pragma unroll
    for (int dz = 0; dz < 3; dz++) {
        int z = zz + dz - 1;
        if (z < 0 || z > 7) continue;
#pragma unroll
        for (int dy = 0; dy < 3; dy++) {
            int y = yy + dy - 1;
            if (y < 0 || y > 7) continue;
#pragma unroll
            for (int dx = 0; dx < 3; dx++) {
                int x = xx + dx - 1;
                if (x < 0 || x > 7) continue;
                acc = fmaf(src[z * 64 + y * 8 + x], wc[dz * 9 + dy * 3 + dx], acc);
            }
        }
    }
    g_q[((size_t)b * NH_KD + c) * N_ + n] = fmaf(acc, scale[c], bias[c]);
}

// ---------------------------------------------------------------------------
// Fused attention per (b, h, 64-row n-tile), 512 threads (16 warps).
// QK^T single pass 8n x 8m fp32x2; softmax; PV 4d x 2n fp32x2.
// ---------------------------------------------------------------------------
__global__ __launch_bounds__(512, 1)
void attn_kernel(const float* __restrict__ attn_biases,
                 const int* __restrict__ bias_idxs)
{
    extern __shared__ float sm[];
    float* S   = sm;               // [64][512]
    float* kvs = sm + 64 * 512;    // 8192 floats: k [16][512], later v [64m][68]
    float* qs  = kvs + 16 * 512;   // [16][64]
    float* ab  = qs + 16 * 64;     // [512]

    const int b  = blockIdx.z, h = blockIdx.y;
    const int n0 = blockIdx.x * 64;
    const int tid = threadIdx.x;

    const float* qb = g_q   + ((size_t)b * NH_KD + h * KDIM) * N_;
    const float* kb = g_qkv + ((size_t)b * HQKV + NH_KD + h * KDIM) * N_;
    const float* vb = g_qkv + ((size_t)b * HQKV + 2 * NH_KD + h * VDIM) * N_;

    // load q tile [16][64]
    if (tid < 256) {
        int r = tid >> 4, c = (tid & 15) * 4;
        *(float4*)&qs[r * 64 + c] = *(const float4*)&qb[(size_t)r * N_ + n0 + c];
    }
    // load k [16][512]
#pragma unroll
    for (int i = 0; i < 4; i++) {
        int e = tid + i * 512;              // float4 index, 2048 total
        int r = e >> 7, c = (e & 127) * 4;
        *(float4*)&kvs[r * 512 + c] = *(const float4*)&kb[(size_t)r * N_ + c];
    }
    if (tid < 128)
        *(float4*)&ab[tid * 4] = *(const float4*)&attn_biases[h * N_ + tid * 4];
    __syncthreads();

    // ---- QK^T: single pass, 8n x 8m per thread, fp32x2 ----
    const float sc = 0.25f;   // KEY_DIM^-0.5
    {
        const int m  = (tid & 63) * 8;
        const int nl = (tid >> 6) * 8;
        ull acc2[8][4];     // [n][m-pair]
#pragma unroll
        for (int i = 0; i < 8; i++)
#pragma unroll
            for (int j = 0; j < 4; j++) acc2[i][j] = 0ULL;

#pragma unroll
        for (int kc = 0; kc < 16; kc++) {
            float4 t0 = *(const float4*)&qs[kc * 64 + nl];
            float4 t1 = *(const float4*)&qs[kc * 64 + nl + 4];
            ull qd[8];
            qd[0] = dup2(t0.x); qd[1] = dup2(t0.y);
            qd[2] = dup2(t0.z); qd[3] = dup2(t0.w);
            qd[4] = dup2(t1.x); qd[5] = dup2(t1.y);
            qd[6] = dup2(t1.z); qd[7] = dup2(t1.w);
            ulonglong2 k0 = *(const ulonglong2*)&kvs[kc * 512 + m];
            ulonglong2 k1 = *(const ulonglong2*)&kvs[kc * 512 + m + 4];
            ull kv2[4] = {k0.x, k0.y, k1.x, k1.y};
#pragma unroll
            for (int i = 0; i < 8; i++)
#pragma unroll
                for (int j = 0; j < 4; j++)
                    ffma2(acc2[i][j], qd[i], kv2[j]);
        }
        // bias gather + store S
#pragma unroll
        for (int i = 0; i < 8; i++) {
            float f[8];
#pragma unroll
            for (int j2 = 0; j2 < 4; j2++) {
                float2 t = unp(acc2[i][j2]);
                f[2 * j2] = t.x; f[2 * j2 + 1] = t.y;
            }
            const int* idxr = bias_idxs + (size_t)(n0 + nl + i) * N_ + m;
#pragma unroll
            for (int j = 0; j < 8; j += 4) {
                int4 id = *(const int4*)&idxr[j];
                float4 o;
                o.x = fmaf(f[j + 0], sc, ab[id.x]);
                o.y = fmaf(f[j + 1], sc, ab[id.y]);
                o.z = fmaf(f[j + 2], sc, ab[id.z]);
                o.w = fmaf(f[j + 3], sc, ab[id.w]);
                *(float4*)&S[(nl + i) * 512 + m + j] = o;
            }
        }
    }
    __syncthreads();

    // ---- softmax: one warp per row, 4 rows per warp ----
    {
        const int warp = tid >> 5, lane = tid & 31;
        for (int r = warp; r < 64; r += 16) {
            float* row = S + r * 512;
            float e[16];
            float mx = -1e30f;
#pragma unroll
            for (int j = 0; j < 16; j++) { e[j] = row[lane + j * 32]; mx = fmaxf(mx, e[j]); }
#pragma unroll
            for (int off = 16; off; off >>= 1)
                mx = fmaxf(mx, __shfl_xor_sync(0xffffffffu, mx, off));
            float sum = 0.f;
#pragma unroll
            for (int j = 0; j < 16; j++) { e[j] = __expf(e[j] - mx); sum += e[j]; }
#pragma unroll
            for (int off = 16; off; off >>= 1)
                sum += __shfl_xor_sync(0xffffffffu, sum, off);
            float inv = 1.f / sum;
#pragma unroll
            for (int j = 0; j < 16; j++) row[lane + j * 32] = e[j] * inv;
        }
    }

    // ---- P·V: out tile [64 d][64 n], 4d x 2n per thread, fp32x2 along d.
    //      v staged v_s[m][d] stride 68 -> conflict-free float4 loads ----
    const int td = (tid & 15) * 4;     // d base (lanes vary d)
    const int tn = (tid >> 4) * 2;     // n base (broadcast within half-warp)
    ull oacc2[2][2];                   // [d-pair][n]
#pragma unroll
    for (int i = 0; i < 2; i++)
#pragma unroll
        for (int j = 0; j < 2; j++) oacc2[i][j] = 0ULL;

#pragma unroll 1
    for (int mt = 0; mt < 8; mt++) {
        const int m0t = mt * 64;
        __syncthreads();   // previous tile's readers done (also fences k reuse)
#pragma unroll
        for (int i = 0; i < 2; i++) {
            int e = tid + i * 512;           // float4 idx, 1024 total
            int r = e >> 4, c = (e & 15) * 4;   // r = d row, c = m col
            float4 v = *(const float4*)&vb[(size_t)r * N_ + m0t + c];
            kvs[(c + 0) * 68 + r] = v.x;
            kvs[(c + 1) * 68 + r] = v.y;
            kvs[(c + 2) * 68 + r] = v.z;
            kvs[(c + 3) * 68 + r] = v.w;
        }
        __syncthreads();
#pragma unroll 4
        for (int mj = 0; mj < 64; mj += 4) {
            ull v2[4][2];
#pragma unroll
            for (int i = 0; i < 4; i++) {
                ulonglong2 t = *(const ulonglong2*)&kvs[(mj + i) * 68 + td];
                v2[i][0] = t.x; v2[i][1] = t.y;
            }
            float p[2][4];
#pragma unroll
            for (int nn = 0; nn < 2; nn++) {
                float4 t = *(const float4*)&S[(tn + nn) * 512 + m0t + mj];
                p[nn][0] = t.x; p[nn][1] = t.y; p[nn][2] = t.z; p[nn][3] = t.w;
            }
#pragma unroll
            for (int nn = 0; nn < 2; nn++)
#pragma unroll
                for (int i = 0; i < 4; i++) {
                    ull pd = dup2(p[nn][i]);
                    ffma2(oacc2[0][nn], v2[i][0], pd);
                    ffma2(oacc2[1][nn], v2[i][1], pd);
                }
        }
    }

    float* ob = g_att + ((size_t)b * DH_ + h * VDIM) * N_;
#pragma unroll
    for (int dp = 0; dp < 2; dp++) {
        float2 fa = unp(oacc2[dp][0]);   // (d0, d1) at n=tn
        float2 fb = unp(oacc2[dp][1]);   // (d0, d1) at n=tn+1
        float2 o0; o0.x = fa.x; o0.y = fb.x;
        float2 o1; o1.x = fa.y; o1.y = fb.y;
        *(float2*)&ob[(size_t)(td + 2 * dp) * N_ + n0 + tn]     = o0;
        *(float2*)&ob[(size_t)(td + 2 * dp + 1) * N_ + n0 + tn] = o1;
    }
}

// ---------------------------------------------------------------------------
extern "C" void kernel_launch(void* const* d_in, const int* in_sizes, int n_in,
                              void* d_out, int out_size)
{
    const float* x          = (const float*)d_in[0];
    const float* qkv_w      = (const float*)d_in[1];
    const float* qkv_scale  = (const float*)d_in[2];
    const float* qkv_bias   = (const float*)d_in[3];
    const float* dw_w       = (const float*)d_in[4];
    const float* dw_scale   = (const float*)d_in[5];
    const float* dw_bias    = (const float*)d_in[6];
    const float* attn_bias  = (const float*)d_in[7];
    const float* proj_w     = (const float*)d_in[8];
    const float* proj_scale = (const float*)d_in[9];
    const float* proj_bias  = (const float*)d_in[10];
    const int*   bias_idxs  = (const int*)d_in[11];
    float* out = (float*)d_out;

    float *qkv_p, *att_p;
    cudaGetSymbolAddress((void**)&qkv_p, g_qkv);
    cudaGetSymbolAddress((void**)&att_p, g_att);

    const int attn_smem = 169984;
    cudaFuncSetAttribute(attn_kernel,
                         cudaFuncAttributeMaxDynamicSharedMemorySize, attn_smem);

    // 1) QKV pointwise conv + scale/bias:  [768,256] @ [256,512] per batch
    dim3 g1(N_ / 128, HQKV / 128, B_);
    gemm_cbn<DIM_, false><<<g1, 256>>>(qkv_w, x, qkv_p, qkv_scale, qkv_bias,
                                       HQKV, N_);

    // 2) depthwise 3x3x3 conv on q
    dwconv_kernel<<<(B_ * NH_KD * N_) / 256, 256>>>(dw_w, dw_scale, dw_bias);

    // 3) fused attention
    dim3 g2(N_ / 64, NHEADS, B_);
    attn_kernel<<<g2, 512, attn_smem>>>(attn_bias, bias_idxs);

    // 4) relu + proj:  [256,512] @ relu([512,512]) per batch
    dim3 g3(N_ / 128, DIM_ / 128, B_);
    gemm_cbn<DH_, true><<<g3, 256>>>(proj_w, att_p, out, proj_scale, proj_bias,
                                     DIM_, N_);
}

// round 9
// speedup vs baseline: 1.3293x; 1.3293x over previous
#include <cuda_runtime.h>
#include <cuda_bf16.h>

#define B_      32
#define DIM_    256
#define N_      512
#define NHEADS  8
#define KDIM    16
#define NH_KD   128
#define DH_     512
#define HQKV    768
#define VDIM    64

typedef unsigned long long ull;

__device__ __forceinline__ ull dup2(float x) {
    ull r; asm("mov.b64 %0, {%1, %1};" : "=l"(r) : "f"(x)); return r;
}
__device__ __forceinline__ void ffma2(ull& d, ull a, ull b) {
    asm("fma.rn.f32x2 %0, %1, %2, %0;" : "+l"(d) : "l"(a), "l"(b));
}
__device__ __forceinline__ float2 unp(ull v) {
    float2 f; asm("mov.b64 {%0, %1}, %2;" : "=f"(f.x), "=f"(f.y) : "l"(v)); return f;
}

// bf16 helpers
__device__ __forceinline__ unsigned bpack(__nv_bfloat16 a, __nv_bfloat16 b) {
    __nv_bfloat162 t = __halves2bfloat162(a, b);
    return *(unsigned*)&t;
}
__device__ __forceinline__ void mma_bf16(float* c, const unsigned* a, const unsigned* b) {
    asm volatile(
        "mma.sync.aligned.m16n8k16.row.col.f32.bf16.bf16.f32 "
        "{%0,%1,%2,%3}, {%4,%5,%6,%7}, {%8,%9}, {%0,%1,%2,%3};"
        : "+f"(c[0]), "+f"(c[1]), "+f"(c[2]), "+f"(c[3])
        : "r"(a[0]), "r"(a[1]), "r"(a[2]), "r"(a[3]), "r"(b[0]), "r"(b[1]));
}

// Scratch (device globals: no allocation allowed)
__device__ float g_qkv[(size_t)B_ * HQKV * N_];   // [b][768][512]
__device__ float g_q  [(size_t)B_ * NH_KD * N_];  // dw-conv output
__device__ float g_att[(size_t)B_ * DH_ * N_];    // attention output (pre-relu)

// ---------------------------------------------------------------------------
// CBN GEMM (unchanged from best round): 128x128, BK=8, fp32x2, double-buffered
// ---------------------------------------------------------------------------
template <int K, bool RELU_B>
__global__ __launch_bounds__(256, 2)
void gemm_cbn(const float* __restrict__ A, const float* __restrict__ Bg,
              float* __restrict__ Cg, const float* __restrict__ scale,
              const float* __restrict__ bias, int M, int N)
{
    const int b = blockIdx.z;
    const float* Bb = Bg + (size_t)b * K * N;
    float* Cb = Cg + (size_t)b * M * N;
    const int m0 = blockIdx.y * 128;
    const int n0 = blockIdx.x * 128;
    const int tid = threadIdx.x;

    __shared__ float As[2][8][128];
    __shared__ float Bs[2][8][128];

    const int ty = tid >> 4, tx = tid & 15;
    const int ar = tid >> 1, ac = (tid & 1) * 4;
    const int br = tid >> 5, bc = (tid & 31) * 4;

    const float* Aptr = &A[(size_t)(m0 + ar) * K + ac];
    const float* Bptr = &Bb[(size_t)br * N + n0 + bc];

    ull acc2[2][2][8];
#pragma unroll
    for (int ih = 0; ih < 2; ih++)
#pragma unroll
        for (int i2 = 0; i2 < 2; i2++)
#pragma unroll
            for (int j = 0; j < 8; j++) acc2[ih][i2][j] = 0ULL;

    {
        float4 a = *(const float4*)Aptr;
        As[0][ac + 0][ar] = a.x; As[0][ac + 1][ar] = a.y;
        As[0][ac + 2][ar] = a.z; As[0][ac + 3][ar] = a.w;
        float4 v = *(const float4*)Bptr;
        if (RELU_B) {
            v.x = fmaxf(v.x, 0.f); v.y = fmaxf(v.y, 0.f);
            v.z = fmaxf(v.z, 0.f); v.w = fmaxf(v.w, 0.f);
        }
        *(float4*)&Bs[0][br][bc] = v;
    }
    __syncthreads();

    constexpr int T = K / 8;
#pragma unroll 2
    for (int t = 0; t < T; t++) {
        const int cur = t & 1;
        float4 na, nb;
        if (t + 1 < T) {
            na = *(const float4*)(Aptr + (t + 1) * 8);
            nb = *(const float4*)(Bptr + (size_t)(t + 1) * 8 * N);
        }

#pragma unroll
        for (int kk = 0; kk < 8; kk++) {
            ull a2[2][2];
            {
                ulonglong2 t0 = *(const ulonglong2*)&As[cur][kk][ty * 4];
                a2[0][0] = t0.x; a2[0][1] = t0.y;
                ulonglong2 t1 = *(const ulonglong2*)&As[cur][kk][64 + ty * 4];
                a2[1][0] = t1.x; a2[1][1] = t1.y;
            }
            float4 bl = *(const float4*)&Bs[cur][kk][tx * 4];
            float4 bh = *(const float4*)&Bs[cur][kk][64 + tx * 4];
            ull bd[8];
            bd[0] = dup2(bl.x); bd[1] = dup2(bl.y);
            bd[2] = dup2(bl.z); bd[3] = dup2(bl.w);
            bd[4] = dup2(bh.x); bd[5] = dup2(bh.y);
            bd[6] = dup2(bh.z); bd[7] = dup2(bh.w);
#pragma unroll
            for (int ih = 0; ih < 2; ih++)
#pragma unroll
                for (int i2 = 0; i2 < 2; i2++)
#pragma unroll
                    for (int j = 0; j < 8; j++)
                        ffma2(acc2[ih][i2][j], a2[ih][i2], bd[j]);
        }

        if (t + 1 < T) {
            const int nxt = cur ^ 1;
            As[nxt][ac + 0][ar] = na.x; As[nxt][ac + 1][ar] = na.y;
            As[nxt][ac + 2][ar] = na.z; As[nxt][ac + 3][ar] = na.w;
            if (RELU_B) {
                nb.x = fmaxf(nb.x, 0.f); nb.y = fmaxf(nb.y, 0.f);
                nb.z = fmaxf(nb.z, 0.f); nb.w = fmaxf(nb.w, 0.f);
            }
            *(float4*)&Bs[nxt][br][bc] = nb;
        }
        __syncthreads();
    }

#pragma unroll
    for (int ih = 0; ih < 2; ih++) {
#pragma unroll
        for (int i2 = 0; i2 < 2; i2++) {
            const int mA = m0 + ih * 64 + ty * 4 + 2 * i2;
            float fl[8], fh[8];
#pragma unroll
            for (int j = 0; j < 8; j++) {
                float2 f = unp(acc2[ih][i2][j]);
                fl[j] = f.x; fh[j] = f.y;
            }
            float sL = scale[mA],     bL = bias[mA];
            float sH = scale[mA + 1], bH = bias[mA + 1];
            float4 o;
            o.x = fmaf(fl[0], sL, bL); o.y = fmaf(fl[1], sL, bL);
            o.z = fmaf(fl[2], sL, bL); o.w = fmaf(fl[3], sL, bL);
            *(float4*)&Cb[(size_t)mA * N + n0 + tx * 4] = o;
            o.x = fmaf(fl[4], sL, bL); o.y = fmaf(fl[5], sL, bL);
            o.z = fmaf(fl[6], sL, bL); o.w = fmaf(fl[7], sL, bL);
            *(float4*)&Cb[(size_t)mA * N + n0 + 64 + tx * 4] = o;
            o.x = fmaf(fh[0], sH, bH); o.y = fmaf(fh[1], sH, bH);
            o.z = fmaf(fh[2], sH, bH); o.w = fmaf(fh[3], sH, bH);
            *(float4*)&Cb[(size_t)(mA + 1) * N + n0 + tx * 4] = o;
            o.x = fmaf(fh[4], sH, bH); o.y = fmaf(fh[5], sH, bH);
            o.z = fmaf(fh[6], sH, bH); o.w = fmaf(fh[7], sH, bH);
            *(float4*)&Cb[(size_t)(mA + 1) * N + n0 + 64 + tx * 4] = o;
        }
    }
}

// ---------------------------------------------------------------------------
// Depthwise 3x3x3 conv on q channels, pad=1, then scale/bias.
// ---------------------------------------------------------------------------
__global__ __launch_bounds__(256)
void dwconv_kernel(const float* __restrict__ w,
                   const float* __restrict__ scale,
                   const float* __restrict__ bias)
{
    int idx = blockIdx.x * 256 + threadIdx.x;     // B*128*512 threads
    int n = idx & 511;
    int c = (idx >> 9) & 127;
    int b = idx >> 16;
    int xx = n & 7, yy = (n >> 3) & 7, zz = n >> 6;

    const float* src = g_qkv + ((size_t)b * HQKV + c) * N_;
    const float* wc = w + c * 27;
    float acc = 0.f;
#pragma unroll
    for (int dz = 0; dz < 3; dz++) {
        int z = zz + dz - 1;
        if (z < 0 || z > 7) continue;
#pragma unroll
        for (int dy = 0; dy < 3; dy++) {
            int y = yy + dy - 1;
            if (y < 0 || y > 7) continue;
#pragma unroll
            for (int dx = 0; dx < 3; dx++) {
                int x = xx + dx - 1;
                if (x < 0 || x > 7) continue;
                acc = fmaf(src[z * 64 + y * 8 + x], wc[dz * 9 + dy * 3 + dx], acc);
            }
        }
    }
    g_q[((size_t)b * NH_KD + c) * N_ + n] = fmaf(acc, scale[c], bias[c]);
}

// ---------------------------------------------------------------------------
// Fused attention per (b, h, 64-row n-tile), 512 threads (16 warps).
// QK^T and P·V on tensor cores: mma.m16n8k16 bf16 with bf16x3 split
// (x = hi + lo; hi*hi + lo*hi + hi*lo) for near-fp32 accuracy.
// Phase 1: S[64][512] fp32 in SMEM (mma + bias-gather epilogue)
// Phase 2: softmax rows (unchanged)
// Phase 3: P·V per 64-m tile, V staged split-bf16 [d][m] (pad 72)
// SMEM: S 131072 + ab 2048 + q 2x1280 + k 2x10240 + v 2x4608 bf16 = 197632 B
// ---------------------------------------------------------------------------
__global__ __launch_bounds__(512, 1)
void attn_kernel(const float* __restrict__ attn_biases,
                 const int* __restrict__ bias_idxs)
{
    extern __shared__ float sm[];
    float* S  = sm;                       // [64][512] fp32
    float* ab = sm + 32768;               // [512]
    __nv_bfloat16* qhi = (__nv_bfloat16*)(sm + 33280);  // [64][20]
    __nv_bfloat16* qlo = qhi + 1280;
    __nv_bfloat16* khi = qlo + 1280;                    // [512][20]
    __nv_bfloat16* klo = khi + 10240;
    __nv_bfloat16* vhi = klo + 10240;                   // [64][72]
    __nv_bfloat16* vlo = vhi + 4608;

    const int b  = blockIdx.z, h = blockIdx.y;
    const int n0 = blockIdx.x * 64;
    const int tid = threadIdx.x;
    const int warp = tid >> 5, lane = tid & 31;
    const int r  = lane >> 2;          // fragment row group
    const int c2 = (lane & 3) * 2;     // fragment col pair base

    const float* qb = g_q   + ((size_t)b * NH_KD + h * KDIM) * N_;
    const float* kb = g_qkv + ((size_t)b * HQKV + NH_KD + h * KDIM) * N_;
    const float* vb = g_qkv + ((size_t)b * HQKV + 2 * NH_KD + h * VDIM) * N_;

    // ---- stage qT [n][k] split bf16 (1024 elems) ----
#pragma unroll
    for (int i = 0; i < 2; i++) {
        int e = tid + i * 512;
        int k = e >> 6, n = e & 63;
        float x = qb[(size_t)k * N_ + n0 + n];
        __nv_bfloat16 hi = __float2bfloat16_rn(x);
        qhi[n * 20 + k] = hi;
        qlo[n * 20 + k] = __float2bfloat16_rn(x - __bfloat162float(hi));
    }
    // ---- stage kT [m][k] split bf16 (8192 elems) ----
#pragma unroll
    for (int i = 0; i < 16; i++) {
        int e = tid + i * 512;
        int k = e >> 9, m = e & 511;
        float x = kb[(size_t)k * N_ + m];
        __nv_bfloat16 hi = __float2bfloat16_rn(x);
        khi[m * 20 + k] = hi;
        klo[m * 20 + k] = __float2bfloat16_rn(x - __bfloat162float(hi));
    }
    ab[tid] = attn_biases[h * N_ + tid];
    __syncthreads();

    // ---- Phase 1: S = q^T k * 0.25 + bias ----
    const int nt = (warp & 3) * 16;       // warp's 16 n-rows
    {
        const int mbase = (warp >> 2) * 128;   // warp's 128 m-cols
        unsigned ah[4], al[4];
        ah[0] = *(const unsigned*)&qhi[(nt + r) * 20 + c2];
        ah[1] = *(const unsigned*)&qhi[(nt + r + 8) * 20 + c2];
        ah[2] = *(const unsigned*)&qhi[(nt + r) * 20 + c2 + 8];
        ah[3] = *(const unsigned*)&qhi[(nt + r + 8) * 20 + c2 + 8];
        al[0] = *(const unsigned*)&qlo[(nt + r) * 20 + c2];
        al[1] = *(const unsigned*)&qlo[(nt + r + 8) * 20 + c2];
        al[2] = *(const unsigned*)&qlo[(nt + r) * 20 + c2 + 8];
        al[3] = *(const unsigned*)&qlo[(nt + r + 8) * 20 + c2 + 8];

#pragma unroll
        for (int mt = 0; mt < 16; mt++) {
            const int m0w = mbase + mt * 8;
            unsigned bh[2], bl2[2];
            bh[0]  = *(const unsigned*)&khi[(m0w + r) * 20 + c2];
            bh[1]  = *(const unsigned*)&khi[(m0w + r) * 20 + c2 + 8];
            bl2[0] = *(const unsigned*)&klo[(m0w + r) * 20 + c2];
            bl2[1] = *(const unsigned*)&klo[(m0w + r) * 20 + c2 + 8];
            float c[4] = {0.f, 0.f, 0.f, 0.f};
            mma_bf16(c, ah, bh);
            mma_bf16(c, al, bh);
            mma_bf16(c, ah, bl2);

            const int nr0 = nt + r, nr1 = nt + r + 8;
            const int mc = m0w + c2;
            int2 i0 = *(const int2*)&bias_idxs[(size_t)(n0 + nr0) * N_ + mc];
            int2 i1 = *(const int2*)&bias_idxs[(size_t)(n0 + nr1) * N_ + mc];
            float2 o0, o1;
            o0.x = fmaf(c[0], 0.25f, ab[i0.x]);
            o0.y = fmaf(c[1], 0.25f, ab[i0.y]);
            o1.x = fmaf(c[2], 0.25f, ab[i1.x]);
            o1.y = fmaf(c[3], 0.25f, ab[i1.y]);
            *(float2*)&S[nr0 * 512 + mc] = o0;
            *(float2*)&S[nr1 * 512 + mc] = o1;
        }
    }
    __syncthreads();

    // ---- Phase 2: softmax, one warp per row, 4 rows per warp ----
    for (int rr = warp; rr < 64; rr += 16) {
        float* row = S + rr * 512;
        float e[16];
        float mx = -1e30f;
#pragma unroll
        for (int j = 0; j < 16; j++) { e[j] = row[lane + j * 32]; mx = fmaxf(mx, e[j]); }
#pragma unroll
        for (int off = 16; off; off >>= 1)
            mx = fmaxf(mx, __shfl_xor_sync(0xffffffffu, mx, off));
        float sum = 0.f;
#pragma unroll
        for (int j = 0; j < 16; j++) { e[j] = __expf(e[j] - mx); sum += e[j]; }
#pragma unroll
        for (int off = 16; off; off >>= 1)
            sum += __shfl_xor_sync(0xffffffffu, sum, off);
        float inv = 1.f / sum;
#pragma unroll
        for (int j = 0; j < 16; j++) row[lane + j * 32] = e[j] * inv;
    }

    // ---- Phase 3: O[n][d] = P @ V^T over 8 m-tiles of 64 ----
    const int dbase = (warp >> 2) * 16;   // warp's 16 d-cols (2 mma tiles)
    float oacc[2][4];
#pragma unroll
    for (int i = 0; i < 2; i++)
#pragma unroll
        for (int j = 0; j < 4; j++) oacc[i][j] = 0.f;

#pragma unroll 1
    for (int mt = 0; mt < 8; mt++) {
        const int m0t = mt * 64;
        __syncthreads();   // previous tile's mma readers done (also post-softmax)
        // stage v tile: [d][m] split bf16, row pad 72
#pragma unroll
        for (int i = 0; i < 2; i++) {
            int e = tid + i * 512;
            int d = e >> 4, mc = (e & 15) * 4;
            float4 v = *(const float4*)&vb[(size_t)d * N_ + m0t + mc];
            float vv[4] = {v.x, v.y, v.z, v.w};
#pragma unroll
            for (int j = 0; j < 4; j++) {
                __nv_bfloat16 hi = __float2bfloat16_rn(vv[j]);
                vhi[d * 72 + mc + j] = hi;
                vlo[d * 72 + mc + j] = __float2bfloat16_rn(vv[j] - __bfloat162float(hi));
            }
        }
        __syncthreads();

#pragma unroll
        for (int ks = 0; ks < 4; ks++) {
            // A = P fragment from S (fp32 -> split bf16 on the fly)
            const int kc = m0t + ks * 16 + c2;
            float2 p00 = *(const float2*)&S[(nt + r) * 512 + kc];
            float2 p10 = *(const float2*)&S[(nt + r + 8) * 512 + kc];
            float2 p01 = *(const float2*)&S[(nt + r) * 512 + kc + 8];
            float2 p11 = *(const float2*)&S[(nt + r + 8) * 512 + kc + 8];
            unsigned ah[4], al[4];
            {
                __nv_bfloat16 h0 = __float2bfloat16_rn(p00.x), h1 = __float2bfloat16_rn(p00.y);
                ah[0] = bpack(h0, h1);
                al[0] = bpack(__float2bfloat16_rn(p00.x - __bfloat162float(h0)),
                              __float2bfloat16_rn(p00.y - __bfloat162float(h1)));
                h0 = __float2bfloat16_rn(p10.x); h1 = __float2bfloat16_rn(p10.y);
                ah[1] = bpack(h0, h1);
                al[1] = bpack(__float2bfloat16_rn(p10.x - __bfloat162float(h0)),
                              __float2bfloat16_rn(p10.y - __bfloat162float(h1)));
                h0 = __float2bfloat16_rn(p01.x); h1 = __float2bfloat16_rn(p01.y);
                ah[2] = bpack(h0, h1);
                al[2] = bpack(__float2bfloat16_rn(p01.x - __bfloat162float(h0)),
                              __float2bfloat16_rn(p01.y - __bfloat162float(h1)));
                h0 = __float2bfloat16_rn(p11.x); h1 = __float2bfloat16_rn(p11.y);
                ah[3] = bpack(h0, h1);
                al[3] = bpack(__float2bfloat16_rn(p11.x - __bfloat162float(h0)),
                              __float2bfloat16_rn(p11.y - __bfloat162float(h1)));
            }
#pragma unroll
            for (int dt = 0; dt < 2; dt++) {
                const int d = dbase + dt * 8 + r;
                const int mk = ks * 16 + c2;
                unsigned bh[2], bl2[2];
                bh[0]  = *(const unsigned*)&vhi[d * 72 + mk];
                bh[1]  = *(const unsigned*)&vhi[d * 72 + mk + 8];
                bl2[0] = *(const unsigned*)&vlo[d * 72 + mk];
                bl2[1] = *(const unsigned*)&vlo[d * 72 + mk + 8];
                mma_bf16(oacc[dt], ah, bh);
                mma_bf16(oacc[dt], al, bh);
                mma_bf16(oacc[dt], ah, bl2);
            }
        }
    }

    // ---- O epilogue: oacc c0..c3 at (n = nt+r(+8), d = dbase+dt*8+c2(+1)) ----
    float* ob = g_att + ((size_t)b * DH_ + h * VDIM) * N_;
#pragma unroll
    for (int dt = 0; dt < 2; dt++) {
        const int d = dbase + dt * 8 + c2;
        const int nr0 = n0 + nt + r, nr1 = n0 + nt + r + 8;
        ob[(size_t)d * N_ + nr0]       = oacc[dt][0];
        ob[(size_t)(d + 1) * N_ + nr0] = oacc[dt][1];
        ob[(size_t)d * N_ + nr1]       = oacc[dt][2];
        ob[(size_t)(d + 1) * N_ + nr1] = oacc[dt][3];
    }
}

// ---------------------------------------------------------------------------
extern "C" void kernel_launch(void* const* d_in, const int* in_sizes, int n_in,
                              void* d_out, int out_size)
{
    const float* x          = (const float*)d_in[0];
    const float* qkv_w      = (const float*)d_in[1];
    const float* qkv_scale  = (const float*)d_in[2];
    const float* qkv_bias   = (const float*)d_in[3];
    const float* dw_w       = (const float*)d_in[4];
    const float* dw_scale   = (const float*)d_in[5];
    const float* dw_bias    = (const float*)d_in[6];
    const float* attn_bias  = (const float*)d_in[7];
    const float* proj_w     = (const float*)d_in[8];
    const float* proj_scale = (const float*)d_in[9];
    const float* proj_bias  = (const float*)d_in[10];
    const int*   bias_idxs  = (const int*)d_in[11];
    float* out = (float*)d_out;

    float *qkv_p, *att_p;
    cudaGetSymbolAddress((void**)&qkv_p, g_qkv);
    cudaGetSymbolAddress((void**)&att_p, g_att);

    const int attn_smem = 197632;
    cudaFuncSetAttribute(attn_kernel,
                         cudaFuncAttributeMaxDynamicSharedMemorySize, attn_smem);

    // 1) QKV pointwise conv + scale/bias:  [768,256] @ [256,512] per batch
    dim3 g1(N_ / 128, HQKV / 128, B_);
    gemm_cbn<DIM_, false><<<g1, 256>>>(qkv_w, x, qkv_p, qkv_scale, qkv_bias,
                                       HQKV, N_);

    // 2) depthwise 3x3x3 conv on q
    dwconv_kernel<<<(B_ * NH_KD * N_) / 256, 256>>>(dw_w, dw_scale, dw_bias);

    // 3) fused attention (tensor cores, bf16x3)
    dim3 g2(N_ / 64, NHEADS, B_);
    attn_kernel<<<g2, 512, attn_smem>>>(attn_bias, bias_idxs);

    // 4) relu + proj:  [256,512] @ relu([512,512]) per batch
    dim3 g3(N_ / 128, DIM_ / 128, B_);
    gemm_cbn<DH_, true><<<g3, 256>>>(proj_w, att_p, out, proj_scale, proj_bias,
                                     DIM_, N_);
}

// round 11
// speedup vs baseline: 1.5850x; 1.1924x over previous
#include <cuda_runtime.h>
#include <cuda_bf16.h>

#define B_      32
#define DIM_    256
#define N_      512
#define NHEADS  8
#define KDIM    16
#define NH_KD   128
#define DH_     512
#define HQKV    768
#define VDIM    64

typedef unsigned long long ull;

// ---------------------------------------------------------------------------
// helpers
// ---------------------------------------------------------------------------
__device__ __forceinline__ unsigned prmt_(unsigned a, unsigned b, unsigned s) {
    unsigned d; asm("prmt.b32 %0, %1, %2, %3;" : "=r"(d) : "r"(a), "r"(b), "r"(s));
    return d;
}
// pack bf16 split of x: hi in low 16, lo in high 16
__device__ __forceinline__ unsigned packsplit(float x) {
    __nv_bfloat16 hi = __float2bfloat16_rn(x);
    __nv_bfloat16 lo = __float2bfloat16_rn(x - __bfloat162float(hi));
    unsigned short h = *(unsigned short*)&hi, l = *(unsigned short*)&lo;
    return (unsigned)h | ((unsigned)l << 16);
}
__device__ __forceinline__ void mma_bf16(float* c, const unsigned* a, const unsigned* b) {
    asm volatile(
        "mma.sync.aligned.m16n8k16.row.col.f32.bf16.bf16.f32 "
        "{%0,%1,%2,%3}, {%4,%5,%6,%7}, {%8,%9}, {%0,%1,%2,%3};"
        : "+f"(c[0]), "+f"(c[1]), "+f"(c[2]), "+f"(c[3])
        : "r"(a[0]), "r"(a[1]), "r"(a[2]), "r"(a[3]), "r"(b[0]), "r"(b[1]));
}

// ---------------------------------------------------------------------------
// Scratch (device globals: no allocation allowed)
// ---------------------------------------------------------------------------
__device__ float    g_qkv[(size_t)B_ * HQKV * N_];        // [b][768][512] fp32
__device__ float    g_q  [(size_t)B_ * NH_KD * N_];       // dw-conv out fp32
__device__ float    g_att[(size_t)B_ * DH_ * N_];         // attention out fp32
__device__ unsigned g_wq [(size_t)HQKV * DIM_];           // packed qkv_w [m][k]
__device__ unsigned g_wp [(size_t)DIM_ * DH_];            // packed proj_w [m][k]
__device__ unsigned g_xT [(size_t)B_ * N_ * DIM_];        // packed x^T [b][n][k]
__device__ unsigned g_aT [(size_t)B_ * N_ * DH_];         // packed relu(att)^T
__device__ unsigned g_kp [(size_t)B_ * NHEADS * N_ * KDIM];  // packed k^T [b][h][m][k]
__device__ unsigned g_vp [(size_t)B_ * NHEADS * VDIM * N_];  // packed v [b][h][d][m]

// ---------------------------------------------------------------------------
// prep kernels
// ---------------------------------------------------------------------------
__global__ void pack_kernel(const float* __restrict__ src, unsigned* __restrict__ dst, int n)
{
    int i = blockIdx.x * 256 + threadIdx.x;
    if (i < n) dst[i] = packsplit(src[i]);
}

// src [b][K][N] fp32 -> dst [b][N][K] packed u32 (optional relu)
__global__ void transpose_pack(const float* __restrict__ src, unsigned* __restrict__ dst,
                               int K, int N, int relu)
{
    __shared__ unsigned tile[32][33];
    const int b = blockIdx.z;
    const int k0 = blockIdx.y * 32, n0 = blockIdx.x * 32;
    const int tx = threadIdx.x & 31, ty = threadIdx.x >> 5;
    const float* sb = src + (size_t)b * K * N;
    unsigned* db = dst + (size_t)b * N * K;
#pragma unroll
    for (int i = 0; i < 4; i++) {
        float v = sb[(size_t)(k0 + ty + i * 8) * N + n0 + tx];
        if (relu) v = fmaxf(v, 0.f);
        tile[ty + i * 8][tx] = packsplit(v);
    }
    __syncthreads();
#pragma unroll
    for (int i = 0; i < 4; i++)
        db[(size_t)(n0 + ty + i * 8) * K + k0 + tx] = tile[tx][ty + i * 8];
}

// k channels of g_qkv -> g_kp [b][h][m=512][k=16] packed (transpose via smem)
__global__ void prep_k()
{
    __shared__ unsigned sm[512 * 17];
    const int bh = blockIdx.x;       // b*8 + h
    const int b = bh >> 3, h = bh & 7;
    const int tid = threadIdx.x;
    const float* src = g_qkv + ((size_t)b * HQKV + NH_KD + h * KDIM) * N_;
#pragma unroll
    for (int i = 0; i < 32; i++) {
        int e = tid + i * 256;
        int k = e >> 9, n = e & 511;
        sm[n * 17 + k] = packsplit(src[(size_t)k * N_ + n]);
    }
    __syncthreads();
    unsigned* dst = g_kp + (size_t)bh * N_ * KDIM;
#pragma unroll
    for (int i = 0; i < 32; i++) {
        int e = tid + i * 256;
        int n = e >> 4, k = e & 15;
        dst[e] = sm[n * 17 + k];
    }
}

// v channels of g_qkv -> g_vp [b][h][d][m] packed (no transpose)
__global__ void prep_v()
{
    int idx = blockIdx.x * 256 + threadIdx.x;   // 32*8*64*512
    int m = idx & 511;
    int d = (idx >> 9) & 63;
    int h = (idx >> 15) & 7;
    int b = idx >> 18;
    float v = g_qkv[((size_t)b * HQKV + 2 * NH_KD + h * VDIM + d) * N_ + m];
    g_vp[idx] = packsplit(v);
}

// ---------------------------------------------------------------------------
// Tensor-core CBN GEMM: C[b][M][N] = A[M,K] @ B[b][K,N] (operands pre-packed,
// B pre-transposed to [n][k]); epilogue scale/bias per row m.
// 128x128x32 tiles, 256 thr, 8 warps (4m x 2n), warp tile 32x64, bf16x3.
// cp.async double-buffered. SMEM: 2*(128*36)*2 operands u32 = 73728 B.
// ---------------------------------------------------------------------------
template <int K>
__global__ __launch_bounds__(256, 2)
void gemm_mma(const unsigned* __restrict__ Apk, const unsigned* __restrict__ Bpk,
              float* __restrict__ Cg, const float* __restrict__ scale,
              const float* __restrict__ bias, int M, int N)
{
    extern __shared__ unsigned smu[];
    unsigned* Asb = smu;            // [2][128][36]
    unsigned* Bsb = smu + 9216;     // [2][128][36]

    const int b = blockIdx.z;
    const unsigned* Bb = Bpk + (size_t)b * N * K;
    float* Cb = Cg + (size_t)b * M * N;
    const int m0 = blockIdx.y * 128, n0 = blockIdx.x * 128;
    const int tid = threadIdx.x, warp = tid >> 5, lane = tid & 31;
    const int r = lane >> 2, c2 = (lane & 3) * 2;
    const int wm = warp >> 1, wn = warp & 1;

    float acc[2][8][4];
#pragma unroll
    for (int i = 0; i < 2; i++)
#pragma unroll
        for (int j = 0; j < 8; j++)
#pragma unroll
            for (int q = 0; q < 4; q++) acc[i][j][q] = 0.f;

    auto issue = [&](int t) {
        const int buf = t & 1;
        const int k0 = t * 32;
#pragma unroll
        for (int i = 0; i < 4; i++) {
            int e = tid + i * 256;
            int row = e >> 3, seg = (e & 7) * 4;
            unsigned sa = (unsigned)__cvta_generic_to_shared(&Asb[buf * 4608 + row * 36 + seg]);
            asm volatile("cp.async.cg.shared.global [%0], [%1], 16;" ::
                         "r"(sa), "l"(&Apk[(size_t)(m0 + row) * K + k0 + seg]));
            unsigned sb2 = (unsigned)__cvta_generic_to_shared(&Bsb[buf * 4608 + row * 36 + seg]);
            asm volatile("cp.async.cg.shared.global [%0], [%1], 16;" ::
                         "r"(sb2), "l"(&Bb[(size_t)(n0 + row) * K + k0 + seg]));
        }
        asm volatile("cp.async.commit_group;");
    };

    issue(0);
    constexpr int T = K / 32;
#pragma unroll 1
    for (int t = 0; t < T; t++) {
        if (t + 1 < T) {
            issue(t + 1);
            asm volatile("cp.async.wait_group 1;");
        } else {
            asm volatile("cp.async.wait_group 0;");
        }
        __syncthreads();

        const unsigned* As = Asb + (t & 1) * 4608;
        const unsigned* Bs = Bsb + (t & 1) * 4608;
#pragma unroll
        for (int ks = 0; ks < 32; ks += 16) {
            unsigned ah[2][4], al[2][4];
#pragma unroll
            for (int mt = 0; mt < 2; mt++) {
                const unsigned* Ap = As + (wm * 32 + mt * 16 + r) * 36 + ks + c2;
                ull w0 = *(const ull*)Ap;
                ull w1 = *(const ull*)(Ap + 8 * 36);
                ull w2 = *(const ull*)(Ap + 8);
                ull w3 = *(const ull*)(Ap + 8 * 36 + 8);
                ah[mt][0] = prmt_((unsigned)w0, (unsigned)(w0 >> 32), 0x5410);
                al[mt][0] = prmt_((unsigned)w0, (unsigned)(w0 >> 32), 0x7632);
                ah[mt][1] = prmt_((unsigned)w1, (unsigned)(w1 >> 32), 0x5410);
                al[mt][1] = prmt_((unsigned)w1, (unsigned)(w1 >> 32), 0x7632);
                ah[mt][2] = prmt_((unsigned)w2, (unsigned)(w2 >> 32), 0x5410);
                al[mt][2] = prmt_((unsigned)w2, (unsigned)(w2 >> 32), 0x7632);
                ah[mt][3] = prmt_((unsigned)w3, (unsigned)(w3 >> 32), 0x5410);
                al[mt][3] = prmt_((unsigned)w3, (unsigned)(w3 >> 32), 0x7632);
            }
#pragma unroll
            for (int nt = 0; nt < 8; nt++) {
                const unsigned* Bp = Bs + (wn * 64 + nt * 8 + r) * 36 + ks + c2;
                ull u0 = *(const ull*)Bp;
                ull u1 = *(const ull*)(Bp + 8);
                unsigned bh[2], bl2[2];
                bh[0]  = prmt_((unsigned)u0, (unsigned)(u0 >> 32), 0x5410);
                bl2[0] = prmt_((unsigned)u0, (unsigned)(u0 >> 32), 0x7632);
                bh[1]  = prmt_((unsigned)u1, (unsigned)(u1 >> 32), 0x5410);
                bl2[1] = prmt_((unsigned)u1, (unsigned)(u1 >> 32), 0x7632);
#pragma unroll
                for (int mt = 0; mt < 2; mt++) {
                    mma_bf16(acc[mt][nt], ah[mt], bh);
                    mma_bf16(acc[mt][nt], al[mt], bh);
                    mma_bf16(acc[mt][nt], ah[mt], bl2);
                }
            }
        }
        __syncthreads();
    }

    // epilogue: scale/bias per row m
#pragma unroll
    for (int mt = 0; mt < 2; mt++) {
        const int mr0 = m0 + wm * 32 + mt * 16 + r;
        const int mr1 = mr0 + 8;
        const float s0 = scale[mr0], b0 = bias[mr0];
        const float s1 = scale[mr1], b1 = bias[mr1];
#pragma unroll
        for (int nt = 0; nt < 8; nt++) {
            const int col = n0 + wn * 64 + nt * 8 + c2;
            float2 o0, o1;
            o0.x = fmaf(acc[mt][nt][0], s0, b0);
            o0.y = fmaf(acc[mt][nt][1], s0, b0);
            o1.x = fmaf(acc[mt][nt][2], s1, b1);
            o1.y = fmaf(acc[mt][nt][3], s1, b1);
            *(float2*)&Cb[(size_t)mr0 * N + col] = o0;
            *(float2*)&Cb[(size_t)mr1 * N + col] = o1;
        }
    }
}

// ---------------------------------------------------------------------------
// Depthwise 3x3x3 conv on q channels, pad=1, then scale/bias.
// ---------------------------------------------------------------------------
__global__ __launch_bounds__(256)
void dwconv_kernel(const float* __restrict__ w,
                   const float* __restrict__ scale,
                   const float* __restrict__ bias)
{
    int idx = blockIdx.x * 256 + threadIdx.x;     // B*128*512 threads
    int n = idx & 511;
    int c = (idx >> 9) & 127;
    int b = idx >> 16;
    int xx = n & 7, yy = (n >> 3) & 7, zz = n >> 6;

    const float* src = g_qkv + ((size_t)b * HQKV + c) * N_;
    const float* wc = w + c * 27;
    float acc = 0.f;
#pragma unroll
    for (int dz = 0; dz < 3; dz++) {
        int z = zz + dz - 1;
        if (z < 0 || z > 7) continue;
#pragma unroll
        for (int dy = 0; dy < 3; dy++) {
            int y = yy + dy - 1;
            if (y < 0 || y > 7) continue;
#pragma unroll
            for (int dx = 0; dx < 3; dx++) {
                int x = xx + dx - 1;
                if (x < 0 || x > 7) continue;
                acc = fmaf(src[z * 64 + y * 8 + x], wc[dz * 9 + dy * 3 + dx], acc);
            }
        }
    }
    g_q[((size_t)b * NH_KD + c) * N_ + n] = fmaf(acc, scale[c], bias[c]);
}

// ---------------------------------------------------------------------------
// Fused attention per (b, h, 64-row n-tile), 512 threads.
// All mma operands packed-u32 (hi|lo) + PRMT unpack at fragment load.
// S stride 520 (2-way instead of 8-way conflicts in phase 3).
// SMEM: S[64][520] f32 + ab[512] + qhi/qlo[64][20] bf16 + kpk[512][18] u32
//       + vpk[64][68] u32 = 194560 B
// ---------------------------------------------------------------------------
#define SPITCH 520

__global__ __launch_bounds__(512, 1)
void attn_kernel(const float* __restrict__ attn_biases,
                 const int* __restrict__ bias_idxs)
{
    extern __shared__ float sm[];
    float* S  = sm;                                       // [64][520]
    float* ab = sm + 64 * SPITCH;                         // [512]
    __nv_bfloat16* qhi = (__nv_bfloat16*)(ab + 512);      // [64][20]
    __nv_bfloat16* qlo = qhi + 1280;
    unsigned* kpk = (unsigned*)(qlo + 1280);              // [512][18]
    unsigned* vpk = kpk + 512 * 18;                       // [64][68]

    const int b  = blockIdx.z, h = blockIdx.y;
    const int n0 = blockIdx.x * 64;
    const int tid = threadIdx.x;
    const int warp = tid >> 5, lane = tid & 31;
    const int r  = lane >> 2;
    const int c2 = (lane & 3) * 2;

    const float* qb = g_q + ((size_t)b * NH_KD + h * KDIM) * N_;
    const unsigned* ksrc = g_kp + (size_t)(b * 8 + h) * N_ * KDIM;
    const unsigned* vsrc = g_vp + (size_t)(b * 8 + h) * VDIM * N_;

    // stage qT [n][k] split bf16
#pragma unroll
    for (int i = 0; i < 2; i++) {
        int e = tid + i * 512;
        int k = e >> 6, n = e & 63;
        float x = qb[(size_t)k * N_ + n0 + n];
        __nv_bfloat16 hi = __float2bfloat16_rn(x);
        qhi[n * 20 + k] = hi;
        qlo[n * 20 + k] = __float2bfloat16_rn(x - __bfloat162float(hi));
    }
    // stage packed kT [m][k]
#pragma unroll
    for (int i = 0; i < 16; i++) {
        int e = tid + i * 512;
        kpk[(e >> 4) * 18 + (e & 15)] = ksrc[e];
    }
    ab[tid] = attn_biases[h * N_ + tid];
    __syncthreads();

    // ---- Phase 1: S = q^T k * 0.25 + bias ----
    const int nt = (warp & 3) * 16;
    {
        const int mbase = (warp >> 2) * 128;
        unsigned ah[4], al[4];
        ah[0] = *(const unsigned*)&qhi[(nt + r) * 20 + c2];
        ah[1] = *(const unsigned*)&qhi[(nt + r + 8) * 20 + c2];
        ah[2] = *(const unsigned*)&qhi[(nt + r) * 20 + c2 + 8];
        ah[3] = *(const unsigned*)&qhi[(nt + r + 8) * 20 + c2 + 8];
        al[0] = *(const unsigned*)&qlo[(nt + r) * 20 + c2];
        al[1] = *(const unsigned*)&qlo[(nt + r + 8) * 20 + c2];
        al[2] = *(const unsigned*)&qlo[(nt + r) * 20 + c2 + 8];
        al[3] = *(const unsigned*)&qlo[(nt + r + 8) * 20 + c2 + 8];

#pragma unroll
        for (int mt = 0; mt < 16; mt++) {
            const int m0w = mbase + mt * 8;
            const unsigned* kp = kpk + (m0w + r) * 18 + c2;
            ull u0 = *(const ull*)kp;
            ull u1 = *(const ull*)(kp + 8);
            unsigned bh[2], bl2[2];
            bh[0]  = prmt_((unsigned)u0, (unsigned)(u0 >> 32), 0x5410);
            bl2[0] = prmt_((unsigned)u0, (unsigned)(u0 >> 32), 0x7632);
            bh[1]  = prmt_((unsigned)u1, (unsigned)(u1 >> 32), 0x5410);
            bl2[1] = prmt_((unsigned)u1, (unsigned)(u1 >> 32), 0x7632);
            float c[4] = {0.f, 0.f, 0.f, 0.f};
            mma_bf16(c, ah, bh);
            mma_bf16(c, al, bh);
            mma_bf16(c, ah, bl2);

            const int nr0 = nt + r, nr1 = nt + r + 8;
            const int mc = m0w + c2;
            int2 i0 = *(const int2*)&bias_idxs[(size_t)(n0 + nr0) * N_ + mc];
            int2 i1 = *(const int2*)&bias_idxs[(size_t)(n0 + nr1) * N_ + mc];
            float2 o0, o1;
            o0.x = fmaf(c[0], 0.25f, ab[i0.x]);
            o0.y = fmaf(c[1], 0.25f, ab[i0.y]);
            o1.x = fmaf(c[2], 0.25f, ab[i1.x]);
            o1.y = fmaf(c[3], 0.25f, ab[i1.y]);
            *(float2*)&S[nr0 * SPITCH + mc] = o0;
            *(float2*)&S[nr1 * SPITCH + mc] = o1;
        }
    }
    __syncthreads();

    // ---- Phase 2: softmax; write back PACKED split bf16 into S ----
    for (int rr = warp; rr < 64; rr += 16) {
        float* row = S + rr * SPITCH;
        float e[16];
        float mx = -1e30f;
#pragma unroll
        for (int j = 0; j < 16; j++) { e[j] = row[lane + j * 32]; mx = fmaxf(mx, e[j]); }
#pragma unroll
        for (int off = 16; off; off >>= 1)
            mx = fmaxf(mx, __shfl_xor_sync(0xffffffffu, mx, off));
        float sum = 0.f;
#pragma unroll
        for (int j = 0; j < 16; j++) { e[j] = __expf(e[j] - mx); sum += e[j]; }
#pragma unroll
        for (int off = 16; off; off >>= 1)
            sum += __shfl_xor_sync(0xffffffffu, sum, off);
        float inv = 1.f / sum;
#pragma unroll
        for (int j = 0; j < 16; j++)
            ((unsigned*)row)[lane + j * 32] = packsplit(e[j] * inv);
    }

    // ---- Phase 3: O[n][d] = P @ V^T over 8 m-tiles of 64 ----
    const int dbase = (warp >> 2) * 16;
    const unsigned* Su = (const unsigned*)S;
    float oacc[2][4];
#pragma unroll
    for (int i = 0; i < 2; i++)
#pragma unroll
        for (int j = 0; j < 4; j++) oacc[i][j] = 0.f;

#pragma unroll 1
    for (int mt = 0; mt < 8; mt++) {
        const int m0t = mt * 64;
        __syncthreads();
        // stage packed v tile [d][m]
#pragma unroll
        for (int i = 0; i < 8; i++) {
            int e = tid + i * 512;
            int d = e >> 6, mc = e & 63;
            vpk[d * 68 + mc] = vsrc[(size_t)d * N_ + m0t + mc];
        }
        __syncthreads();

#pragma unroll
        for (int ks = 0; ks < 4; ks++) {
            const int kc = m0t + ks * 16 + c2;
            unsigned ah[4], al[4];
            ull w;
            w = *(const ull*)&Su[(nt + r) * SPITCH + kc];
            ah[0] = prmt_((unsigned)w, (unsigned)(w >> 32), 0x5410);
            al[0] = prmt_((unsigned)w, (unsigned)(w >> 32), 0x7632);
            w = *(const ull*)&Su[(nt + r + 8) * SPITCH + kc];
            ah[1] = prmt_((unsigned)w, (unsigned)(w >> 32), 0x5410);
            al[1] = prmt_((unsigned)w, (unsigned)(w >> 32), 0x7632);
            w = *(const ull*)&Su[(nt + r) * SPITCH + kc + 8];
            ah[2] = prmt_((unsigned)w, (unsigned)(w >> 32), 0x5410);
            al[2] = prmt_((unsigned)w, (unsigned)(w >> 32), 0x7632);
            w = *(const ull*)&Su[(nt + r + 8) * SPITCH + kc + 8];
            ah[3] = prmt_((unsigned)w, (unsigned)(w >> 32), 0x5410);
            al[3] = prmt_((unsigned)w, (unsigned)(w >> 32), 0x7632);

#pragma unroll
            for (int dt = 0; dt < 2; dt++) {
                const unsigned* vp = vpk + (dbase + dt * 8 + r) * 68 + ks * 16 + c2;
                ull u0 = *(const ull*)vp;
                ull u1 = *(const ull*)(vp + 8);
                unsigned bh[2], bl2[2];
                bh[0]  = prmt_((unsigned)u0, (unsigned)(u0 >> 32), 0x5410);
                bl2[0] = prmt_((unsigned)u0, (unsigned)(u0 >> 32), 0x7632);
                bh[1]  = prmt_((unsigned)u1, (unsigned)(u1 >> 32), 0x5410);
                bl2[1] = prmt_((unsigned)u1, (unsigned)(u1 >> 32), 0x7632);
                mma_bf16(oacc[dt], ah, bh);
                mma_bf16(oacc[dt], al, bh);
                mma_bf16(oacc[dt], ah, bl2);
            }
        }
    }

    // ---- O epilogue ----
    float* ob = g_att + ((size_t)b * DH_ + h * VDIM) * N_;
#pragma unroll
    for (int dt = 0; dt < 2; dt++) {
        const int d = dbase + dt * 8 + c2;
        const int nr0 = n0 + nt + r, nr1 = n0 + nt + r + 8;
        ob[(size_t)d * N_ + nr0]       = oacc[dt][0];
        ob[(size_t)(d + 1) * N_ + nr0] = oacc[dt][1];
        ob[(size_t)d * N_ + nr1]       = oacc[dt][2];
        ob[(size_t)(d + 1) * N_ + nr1] = oacc[dt][3];
    }
}

// ---------------------------------------------------------------------------
extern "C" void kernel_launch(void* const* d_in, const int* in_sizes, int n_in,
                              void* d_out, int out_size)
{
    const float* x          = (const float*)d_in[0];
    const float* qkv_w      = (const float*)d_in[1];
    const float* qkv_scale  = (const float*)d_in[2];
    const float* qkv_bias   = (const float*)d_in[3];
    const float* dw_w       = (const float*)d_in[4];
    const float* dw_scale   = (const float*)d_in[5];
    const float* dw_bias    = (const float*)d_in[6];
    const float* attn_bias  = (const float*)d_in[7];
    const float* proj_w     = (const float*)d_in[8];
    const float* proj_scale = (const float*)d_in[9];
    const float* proj_bias  = (const float*)d_in[10];
    const int*   bias_idxs  = (const int*)d_in[11];
    float* out = (float*)d_out;

    float *qkv_p, *att_p;
    unsigned *wq_p, *wp_p, *xT_p, *aT_p;
    cudaGetSymbolAddress((void**)&qkv_p, g_qkv);
    cudaGetSymbolAddress((void**)&att_p, g_att);
    cudaGetSymbolAddress((void**)&wq_p, g_wq);
    cudaGetSymbolAddress((void**)&wp_p, g_wp);
    cudaGetSymbolAddress((void**)&xT_p, g_xT);
    cudaGetSymbolAddress((void**)&aT_p, g_aT);

    const int gemm_smem = 73728;
    const int attn_smem = 194560;
    cudaFuncSetAttribute(gemm_mma<DIM_>,
                         cudaFuncAttributeMaxDynamicSharedMemorySize, gemm_smem);
    cudaFuncSetAttribute(gemm_mma<DH_>,
                         cudaFuncAttributeMaxDynamicSharedMemorySize, gemm_smem);
    cudaFuncSetAttribute(attn_kernel,
                         cudaFuncAttributeMaxDynamicSharedMemorySize, attn_smem);

    // 0) pack weights + transpose/pack x
    pack_kernel<<<(HQKV * DIM_ + 255) / 256, 256>>>(qkv_w, wq_p, HQKV * DIM_);
    pack_kernel<<<(DIM_ * DH_ + 255) / 256, 256>>>(proj_w, wp_p, DIM_ * DH_);
    transpose_pack<<<dim3(N_ / 32, DIM_ / 32, B_), 256>>>(x, xT_p, DIM_, N_, 0);

    // 1) QKV pointwise conv + scale/bias (tensor cores)
    gemm_mma<DIM_><<<dim3(N_ / 128, HQKV / 128, B_), 256, gemm_smem>>>(
        wq_p, xT_p, qkv_p, qkv_scale, qkv_bias, HQKV, N_);

    // 2) depthwise 3x3x3 conv on q
    dwconv_kernel<<<(B_ * NH_KD * N_) / 256, 256>>>(dw_w, dw_scale, dw_bias);

    // 2b) pre-split k and v into packed form
    prep_k<<<B_ * NHEADS, 256>>>();
    prep_v<<<(B_ * NHEADS * VDIM * N_) / 256, 256>>>();

    // 3) fused attention (tensor cores, packed operands)
    attn_kernel<<<dim3(N_ / 64, NHEADS, B_), 512, attn_smem>>>(attn_bias, bias_idxs);

    // 3b) relu + transpose + pack attention output
    transpose_pack<<<dim3(N_ / 32, DH_ / 32, B_), 256>>>(att_p, aT_p, DH_, N_, 1);

    // 4) proj GEMM (tensor cores; relu already applied in prep)
    gemm_mma<DH_><<<dim3(N_ / 128, DIM_ / 128, B_), 256, gemm_smem>>>(
        wp_p, aT_p, out, proj_scale, proj_bias, DIM_, N_);
}

// round 12
// speedup vs baseline: 1.6620x; 1.0485x over previous
#include <cuda_runtime.h>
#include <cuda_bf16.h>

#define B_      32
#define DIM_    256
#define N_      512
#define NHEADS  8
#define KDIM    16
#define NH_KD   128
#define DH_     512
#define HQKV    768
#define VDIM    64

typedef unsigned long long ull;
typedef __nv_bfloat16 bf16;

// ---------------------------------------------------------------------------
// helpers
// ---------------------------------------------------------------------------
__device__ __forceinline__ unsigned bpack(bf16 a, bf16 b) {
    __nv_bfloat162 t = __halves2bfloat162(a, b);
    return *(unsigned*)&t;
}
__device__ __forceinline__ void split2(float x, bf16& hi, bf16& lo) {
    hi = __float2bfloat16_rn(x);
    lo = __float2bfloat16_rn(x - __bfloat162float(hi));
}
__device__ __forceinline__ void mma_bf16(float* c, const unsigned* a, const unsigned* b) {
    asm volatile(
        "mma.sync.aligned.m16n8k16.row.col.f32.bf16.bf16.f32 "
        "{%0,%1,%2,%3}, {%4,%5,%6,%7}, {%8,%9}, {%0,%1,%2,%3};"
        : "+f"(c[0]), "+f"(c[1]), "+f"(c[2]), "+f"(c[3])
        : "r"(a[0]), "r"(a[1]), "r"(a[2]), "r"(a[3]), "r"(b[0]), "r"(b[1]));
}
__device__ __forceinline__ void ldsm4(unsigned* r, const bf16* p) {
    unsigned a = (unsigned)__cvta_generic_to_shared(p);
    asm volatile("ldmatrix.sync.aligned.m8n8.x4.shared.b16 {%0,%1,%2,%3}, [%4];"
                 : "=r"(r[0]), "=r"(r[1]), "=r"(r[2]), "=r"(r[3]) : "r"(a));
}
__device__ __forceinline__ void cp16(void* dst, const void* src) {
    unsigned d = (unsigned)__cvta_generic_to_shared(dst);
    asm volatile("cp.async.cg.shared.global [%0], [%1], 16;" :: "r"(d), "l"(src));
}

// ---------------------------------------------------------------------------
// Scratch (device globals; hi/lo planes stored contiguously: [2][...])
// ---------------------------------------------------------------------------
__device__ float g_qkv[(size_t)B_ * HQKV * N_];
__device__ float g_q  [(size_t)B_ * NH_KD * N_];
__device__ float g_att[(size_t)B_ * DH_ * N_];
__device__ bf16  g_wq [(size_t)2 * HQKV * DIM_];          // [m][k] planes
__device__ bf16  g_wp [(size_t)2 * DIM_ * DH_];
__device__ bf16  g_xT [(size_t)2 * B_ * N_ * DIM_];       // [b][n][k] planes
__device__ bf16  g_aT [(size_t)2 * B_ * N_ * DH_];
__device__ bf16  g_kp [(size_t)2 * B_ * NHEADS * N_ * KDIM];   // [bh][m][k]
__device__ bf16  g_vp [(size_t)2 * B_ * NHEADS * VDIM * N_];   // [bh][d][m]

#define PSK ((size_t)B_ * NHEADS * N_ * KDIM)
#define PSV ((size_t)B_ * NHEADS * VDIM * N_)

// ---------------------------------------------------------------------------
// prep kernels (split into hi/lo planes)
// ---------------------------------------------------------------------------
__global__ void pack_kernel(const float* __restrict__ src, bf16* __restrict__ dst, int n)
{
    int i = blockIdx.x * 256 + threadIdx.x;
    if (i < n) {
        bf16 hi, lo; split2(src[i], hi, lo);
        dst[i] = hi; dst[n + i] = lo;
    }
}

// src [b][K][N] fp32 -> dst [b][N][K] bf16 planes (optional relu)
__global__ void transpose_pack(const float* __restrict__ src, bf16* __restrict__ dst,
                               int K, int N, int relu, size_t ps)
{
    __shared__ float tile[32][33];
    const int b = blockIdx.z;
    const int k0 = blockIdx.y * 32, n0 = blockIdx.x * 32;
    const int tx = threadIdx.x & 31, ty = threadIdx.x >> 5;
    const float* sb = src + (size_t)b * K * N;
    bf16* db = dst + (size_t)b * N * K;
#pragma unroll
    for (int i = 0; i < 4; i++) {
        float v = sb[(size_t)(k0 + ty + i * 8) * N + n0 + tx];
        if (relu) v = fmaxf(v, 0.f);
        tile[ty + i * 8][tx] = v;
    }
    __syncthreads();
#pragma unroll
    for (int i = 0; i < 4; i++) {
        float v = tile[tx][ty + i * 8];
        bf16 hi, lo; split2(v, hi, lo);
        size_t o = (size_t)(n0 + ty + i * 8) * K + k0 + tx;
        db[o] = hi; db[ps + o] = lo;
    }
}

// k channels -> g_kp [bh][m=512][k=16] planes (transpose via smem)
__global__ void prep_k()
{
    __shared__ unsigned sm[512 * 17];
    const int bh = blockIdx.x;
    const int b = bh >> 3, h = bh & 7;
    const int tid = threadIdx.x;
    const float* src = g_qkv + ((size_t)b * HQKV + NH_KD + h * KDIM) * N_;
#pragma unroll
    for (int i = 0; i < 32; i++) {
        int e = tid + i * 256;
        int k = e >> 9, n = e & 511;
        bf16 hi, lo; split2(src[(size_t)k * N_ + n], hi, lo);
        sm[n * 17 + k] = bpack(hi, lo);
    }
    __syncthreads();
    bf16* dst = g_kp + (size_t)bh * N_ * KDIM;
#pragma unroll
    for (int i = 0; i < 32; i++) {
        int e = tid + i * 256;
        unsigned u = sm[(e >> 4) * 17 + (e & 15)];
        unsigned short hs = (unsigned short)(u & 0xffff), ls = (unsigned short)(u >> 16);
        dst[e] = *(bf16*)&hs; dst[PSK + e] = *(bf16*)&ls;
    }
}

// v channels -> g_vp [bh][d][m] planes
__global__ void prep_v()
{
    int idx = blockIdx.x * 256 + threadIdx.x;   // 32*8*64*512
    int m = idx & 511;
    int d = (idx >> 9) & 63;
    int h = (idx >> 15) & 7;
    int b = idx >> 18;
    bf16 hi, lo;
    split2(g_qkv[((size_t)b * HQKV + 2 * NH_KD + h * VDIM + d) * N_ + m], hi, lo);
    g_vp[idx] = hi; g_vp[PSV + idx] = lo;
}

// ---------------------------------------------------------------------------
// Tensor-core CBN GEMM: C[b] = A[M,K] @ B[b][K,N], operands bf16 hi/lo planes
// (A [m][k], B pre-transposed [n][k]). 128x128x32 tiles, 8 warps (4m x 2n),
// ldmatrix fragment loads, cp.async double-buffered.
// SMEM per buffer (halves): As_hi[128][40] @0, As_lo @5120, Bs_hi @10240,
// Bs_lo @15360 -> 20480 halves; 2 buffers = 81920 B.
// ---------------------------------------------------------------------------
template <int K>
__global__ __launch_bounds__(256, 2)
void gemm_mma(const bf16* __restrict__ Apk, const bf16* __restrict__ Bpk,
              float* __restrict__ Cg, const float* __restrict__ scale,
              const float* __restrict__ bias, int M, int N,
              size_t aps, size_t bps)
{
    extern __shared__ bf16 smh[];
    const int b = blockIdx.z;
    const bf16* Bb = Bpk + (size_t)b * N * K;
    float* Cb = Cg + (size_t)b * M * N;
    const int m0 = blockIdx.y * 128, n0 = blockIdx.x * 128;
    const int tid = threadIdx.x, warp = tid >> 5, lane = tid & 31;
    const int r = lane >> 2, c2 = (lane & 3) * 2;
    const int wm = warp >> 1, wn = warp & 1;
    const int lrow = lane & 15, lcol = (lane >> 4) * 8;

    float acc[2][8][4];
#pragma unroll
    for (int i = 0; i < 2; i++)
#pragma unroll
        for (int j = 0; j < 8; j++)
#pragma unroll
            for (int q = 0; q < 4; q++) acc[i][j][q] = 0.f;

    auto issue = [&](int t) {
        const int k0 = t * 32;
        bf16* sb = smh + (t & 1) * 20480;
#pragma unroll
        for (int i = 0; i < 8; i++) {
            int e = tid + i * 256;
            int plane = e >> 9, idx = e & 511;
            int row = idx >> 2, seg = (idx & 3) * 8;
            const bf16* src;
            bf16* dst;
            if (plane == 0)      { src = Apk + (size_t)(m0 + row) * K + k0 + seg;       dst = sb + row * 40 + seg; }
            else if (plane == 1) { src = Apk + aps + (size_t)(m0 + row) * K + k0 + seg; dst = sb + 5120 + row * 40 + seg; }
            else if (plane == 2) { src = Bb + (size_t)(n0 + row) * K + k0 + seg;        dst = sb + 10240 + row * 40 + seg; }
            else                 { src = Bb + bps + (size_t)(n0 + row) * K + k0 + seg;  dst = sb + 15360 + row * 40 + seg; }
            cp16(dst, src);
        }
        asm volatile("cp.async.commit_group;");
    };

    issue(0);
    constexpr int T = K / 32;
#pragma unroll 1
    for (int t = 0; t < T; t++) {
        if (t + 1 < T) {
            issue(t + 1);
            asm volatile("cp.async.wait_group 1;");
        } else {
            asm volatile("cp.async.wait_group 0;");
        }
        __syncthreads();

        const bf16* As = smh + (t & 1) * 20480;
        const bf16* Bs = As + 10240;
#pragma unroll
        for (int ks = 0; ks < 32; ks += 16) {
            unsigned ah[2][4], al[2][4];
#pragma unroll
            for (int mt = 0; mt < 2; mt++) {
                const int row = wm * 32 + mt * 16 + lrow;
                ldsm4(ah[mt], As + row * 40 + ks + lcol);
                ldsm4(al[mt], As + 5120 + row * 40 + ks + lcol);
            }
#pragma unroll
            for (int ng = 0; ng < 4; ng++) {
                const int row = wn * 64 + ng * 16 + lrow;
                unsigned h4[4], l4[4];
                ldsm4(h4, Bs + row * 40 + ks + lcol);
                ldsm4(l4, Bs + 5120 + row * 40 + ks + lcol);
#pragma unroll
                for (int sub = 0; sub < 2; sub++) {
                    unsigned bh[2]  = {h4[sub], h4[sub + 2]};
                    unsigned bl2[2] = {l4[sub], l4[sub + 2]};
                    const int nt = ng * 2 + sub;
#pragma unroll
                    for (int mt = 0; mt < 2; mt++) {
                        mma_bf16(acc[mt][nt], ah[mt], bh);
                        mma_bf16(acc[mt][nt], al[mt], bh);
                        mma_bf16(acc[mt][nt], ah[mt], bl2);
                    }
                }
            }
        }
        __syncthreads();
    }

    // epilogue: scale/bias per row m
#pragma unroll
    for (int mt = 0; mt < 2; mt++) {
        const int mr0 = m0 + wm * 32 + mt * 16 + r;
        const int mr1 = mr0 + 8;
        const float s0 = scale[mr0], b0 = bias[mr0];
        const float s1 = scale[mr1], b1 = bias[mr1];
#pragma unroll
        for (int nt = 0; nt < 8; nt++) {
            const int col = n0 + wn * 64 + nt * 8 + c2;
            float2 o0, o1;
            o0.x = fmaf(acc[mt][nt][0], s0, b0);
            o0.y = fmaf(acc[mt][nt][1], s0, b0);
            o1.x = fmaf(acc[mt][nt][2], s1, b1);
            o1.y = fmaf(acc[mt][nt][3], s1, b1);
            *(float2*)&Cb[(size_t)mr0 * N + col] = o0;
            *(float2*)&Cb[(size_t)mr1 * N + col] = o1;
        }
    }
}

// ---------------------------------------------------------------------------
// Depthwise 3x3x3 conv on q channels, pad=1, then scale/bias.
// ---------------------------------------------------------------------------
__global__ __launch_bounds__(256)
void dwconv_kernel(const float* __restrict__ w,
                   const float* __restrict__ scale,
                   const float* __restrict__ bias)
{
    int idx = blockIdx.x * 256 + threadIdx.x;
    int n = idx & 511;
    int c = (idx >> 9) & 127;
    int b = idx >> 16;
    int xx = n & 7, yy = (n >> 3) & 7, zz = n >> 6;

    const float* src = g_qkv + ((size_t)b * HQKV + c) * N_;
    const float* wc = w + c * 27;
    float acc = 0.f;
#pragma unroll
    for (int dz = 0; dz < 3; dz++) {
        int z = zz + dz - 1;
        if (z < 0 || z > 7) continue;
#pragma unroll
        for (int dy = 0; dy < 3; dy++) {
            int y = yy + dy - 1;
            if (y < 0 || y > 7) continue;
#pragma unroll
            for (int dx = 0; dx < 3; dx++) {
                int x = xx + dx - 1;
                if (x < 0 || x > 7) continue;
                acc = fmaf(src[z * 64 + y * 8 + x], wc[dz * 9 + dy * 3 + dx], acc);
            }
        }
    }
    g_q[((size_t)b * NH_KD + c) * N_ + n] = fmaf(acc, scale[c], bias[c]);
}

// ---------------------------------------------------------------------------
// Fused attention per (b, h, 64-row n-tile), 512 threads.
// Scores AND P stored as bf16 hi/lo planes (Shi/Slo, pitch 520); all mma
// operands via ldmatrix from conflict-free plane layouts.
// SMEM (halves): Shi@0 [64][520], Slo@33280, qhi@66560 [64][24], qlo@68096,
// khi@69632 [512][24], klo@81920, vhi@94208 [64][72], vlo@98816;
// ab (fp32[512]) @half 103424.  Total 208896 B.
// ---------------------------------------------------------------------------
#define SH  0
#define SL  33280
#define QH  66560
#define QL  68096
#define KH  69632
#define KL  81920
#define VH  94208
#define VL  98816

__global__ __launch_bounds__(512, 1)
void attn_kernel(const float* __restrict__ attn_biases,
                 const int* __restrict__ bias_idxs)
{
    extern __shared__ bf16 smh[];
    float* ab = (float*)(smh + 103424);

    const int b  = blockIdx.z, h = blockIdx.y;
    const int bh = b * 8 + h;
    const int n0 = blockIdx.x * 64;
    const int tid = threadIdx.x;
    const int warp = tid >> 5, lane = tid & 31;
    const int r  = lane >> 2, c2 = (lane & 3) * 2;
    const int lrow = lane & 15, lcol = (lane >> 4) * 8;

    const float* qb = g_q + ((size_t)b * NH_KD + h * KDIM) * N_;
    const bf16* khg = g_kp + (size_t)bh * N_ * KDIM;
    const bf16* vhg = g_vp + (size_t)bh * VDIM * N_;

    // stage k planes via cp.async: 2 planes x 512 rows x 16 halves
#pragma unroll
    for (int i = 0; i < 4; i++) {
        int e = tid + i * 512;
        int plane = e >> 10, idx = e & 1023;
        int row = idx >> 1, seg = (idx & 1) * 8;
        const bf16* src = (plane ? khg + PSK : khg) + row * 16 + seg;
        cp16(smh + (plane ? KL : KH) + row * 24 + seg, src);
    }
    asm volatile("cp.async.commit_group;");

    // stage q split (scalar, 1024 elems)
#pragma unroll
    for (int i = 0; i < 2; i++) {
        int e = tid + i * 512;
        int k = e >> 6, n = e & 63;
        bf16 hi, lo; split2(qb[(size_t)k * N_ + n0 + n], hi, lo);
        smh[QH + n * 24 + k] = hi;
        smh[QL + n * 24 + k] = lo;
    }
    ab[tid] = attn_biases[h * N_ + tid];
    asm volatile("cp.async.wait_group 0;");
    __syncthreads();

    // ---- Phase 1: S = q^T k * 0.25 + bias -> split into Shi/Slo ----
    const int nt = (warp & 3) * 16;
    {
        const int mbase = (warp >> 2) * 128;
        unsigned ah[4], al[4];
        ldsm4(ah, smh + QH + (nt + lrow) * 24 + lcol);
        ldsm4(al, smh + QL + (nt + lrow) * 24 + lcol);

#pragma unroll
        for (int mt2 = 0; mt2 < 8; mt2++) {
            const int m16 = mbase + mt2 * 16;
            unsigned kh4[4], kl4[4];
            ldsm4(kh4, smh + KH + (m16 + lrow) * 24 + lcol);
            ldsm4(kl4, smh + KL + (m16 + lrow) * 24 + lcol);
#pragma unroll
            for (int sub = 0; sub < 2; sub++) {
                unsigned bh[2]  = {kh4[sub], kh4[sub + 2]};
                unsigned bl2[2] = {kl4[sub], kl4[sub + 2]};
                float c[4] = {0.f, 0.f, 0.f, 0.f};
                mma_bf16(c, ah, bh);
                mma_bf16(c, al, bh);
                mma_bf16(c, ah, bl2);

                const int nr0 = nt + r, nr1 = nr0 + 8;
                const int mc = m16 + sub * 8 + c2;
                int2 i0 = *(const int2*)&bias_idxs[(size_t)(n0 + nr0) * N_ + mc];
                int2 i1 = *(const int2*)&bias_idxs[(size_t)(n0 + nr1) * N_ + mc];
                float o0 = fmaf(c[0], 0.25f, ab[i0.x]);
                float o1 = fmaf(c[1], 0.25f, ab[i0.y]);
                float o2 = fmaf(c[2], 0.25f, ab[i1.x]);
                float o3 = fmaf(c[3], 0.25f, ab[i1.y]);
                bf16 h0, l0, h1, l1;
                split2(o0, h0, l0); split2(o1, h1, l1);
                *(unsigned*)&smh[SH + nr0 * 520 + mc] = bpack(h0, h1);
                *(unsigned*)&smh[SL + nr0 * 520 + mc] = bpack(l0, l1);
                split2(o2, h0, l0); split2(o3, h1, l1);
                *(unsigned*)&smh[SH + nr1 * 520 + mc] = bpack(h0, h1);
                *(unsigned*)&smh[SL + nr1 * 520 + mc] = bpack(l0, l1);
            }
        }
    }
    __syncthreads();

    // ---- Phase 2: softmax (reconstruct hi+lo, write split P back) ----
    for (int rr = warp; rr < 64; rr += 16) {
        const int base = rr * 520;
        float e[16];
        float mx = -1e30f;
#pragma unroll
        for (int j = 0; j < 16; j++) {
            int o = base + lane + j * 32;
            e[j] = __bfloat162float(smh[SH + o]) + __bfloat162float(smh[SL + o]);
            mx = fmaxf(mx, e[j]);
        }
#pragma unroll
        for (int off = 16; off; off >>= 1)
            mx = fmaxf(mx, __shfl_xor_sync(0xffffffffu, mx, off));
        float sum = 0.f;
#pragma unroll
        for (int j = 0; j < 16; j++) { e[j] = __expf(e[j] - mx); sum += e[j]; }
#pragma unroll
        for (int off = 16; off; off >>= 1)
            sum += __shfl_xor_sync(0xffffffffu, sum, off);
        float inv = 1.f / sum;
#pragma unroll
        for (int j = 0; j < 16; j++) {
            bf16 hi, lo; split2(e[j] * inv, hi, lo);
            int o = base + lane + j * 32;
            smh[SH + o] = hi; smh[SL + o] = lo;
        }
    }

    // ---- Phase 3: O[n][d] = P @ V^T over 8 m-tiles of 64 ----
    const int dbase = (warp >> 2) * 16;
    float oacc[2][4];
#pragma unroll
    for (int i = 0; i < 2; i++)
#pragma unroll
        for (int j = 0; j < 4; j++) oacc[i][j] = 0.f;

#pragma unroll 1
    for (int mt = 0; mt < 8; mt++) {
        const int m0t = mt * 64;
        __syncthreads();   // previous tile's ldmatrix readers done / post-softmax
        // stage v planes: 2 x 64 rows x 64 halves
#pragma unroll
        for (int i = 0; i < 2; i++) {
            int e = tid + i * 512;
            int plane = e >> 9, idx = e & 511;
            int d = idx >> 3, seg = (idx & 7) * 8;
            const bf16* src = (plane ? vhg + PSV : vhg) + (size_t)d * N_ + m0t + seg;
            cp16(smh + (plane ? VL : VH) + d * 72 + seg, src);
        }
        asm volatile("cp.async.commit_group;");
        asm volatile("cp.async.wait_group 0;");
        __syncthreads();

#pragma unroll
        for (int ks = 0; ks < 4; ks++) {
            const int kcb = m0t + ks * 16;
            unsigned ph[4], pl[4];
            ldsm4(ph, smh + SH + (nt + lrow) * 520 + kcb + lcol);
            ldsm4(pl, smh + SL + (nt + lrow) * 520 + kcb + lcol);
            unsigned vh4[4], vl4[4];
            ldsm4(vh4, smh + VH + (dbase + lrow) * 72 + ks * 16 + lcol);
            ldsm4(vl4, smh + VL + (dbase + lrow) * 72 + ks * 16 + lcol);
#pragma unroll
            for (int dt = 0; dt < 2; dt++) {
                unsigned bh[2]  = {vh4[dt], vh4[dt + 2]};
                unsigned bl2[2] = {vl4[dt], vl4[dt + 2]};
                mma_bf16(oacc[dt], ph, bh);
                mma_bf16(oacc[dt], pl, bh);
                mma_bf16(oacc[dt], ph, bl2);
            }
        }
    }

    // ---- O epilogue ----
    float* ob = g_att + ((size_t)b * DH_ + h * VDIM) * N_;
#pragma unroll
    for (int dt = 0; dt < 2; dt++) {
        const int d = dbase + dt * 8 + c2;
        const int nr0 = n0 + nt + r, nr1 = n0 + nt + r + 8;
        ob[(size_t)d * N_ + nr0]       = oacc[dt][0];
        ob[(size_t)(d + 1) * N_ + nr0] = oacc[dt][1];
        ob[(size_t)d * N_ + nr1]       = oacc[dt][2];
        ob[(size_t)(d + 1) * N_ + nr1] = oacc[dt][3];
    }
}

// ---------------------------------------------------------------------------
extern "C" void kernel_launch(void* const* d_in, const int* in_sizes, int n_in,
                              void* d_out, int out_size)
{
    const float* x          = (const float*)d_in[0];
    const float* qkv_w      = (const float*)d_in[1];
    const float* qkv_scale  = (const float*)d_in[2];
    const float* qkv_bias   = (const float*)d_in[3];
    const float* dw_w       = (const float*)d_in[4];
    const float* dw_scale   = (const float*)d_in[5];
    const float* dw_bias    = (const float*)d_in[6];
    const float* attn_bias  = (const float*)d_in[7];
    const float* proj_w     = (const float*)d_in[8];
    const float* proj_scale = (const float*)d_in[9];
    const float* proj_bias  = (const float*)d_in[10];
    const int*   bias_idxs  = (const int*)d_in[11];
    float* out = (float*)d_out;

    float *qkv_p, *att_p;
    bf16 *wq_p, *wp_p, *xT_p, *aT_p;
    cudaGetSymbolAddress((void**)&qkv_p, g_qkv);
    cudaGetSymbolAddress((void**)&att_p, g_att);
    cudaGetSymbolAddress((void**)&wq_p, g_wq);
    cudaGetSymbolAddress((void**)&wp_p, g_wp);
    cudaGetSymbolAddress((void**)&xT_p, g_xT);
    cudaGetSymbolAddress((void**)&aT_p, g_aT);

    const int gemm_smem = 81920;
    const int attn_smem = 208896;
    cudaFuncSetAttribute(gemm_mma<DIM_>,
                         cudaFuncAttributeMaxDynamicSharedMemorySize, gemm_smem);
    cudaFuncSetAttribute(gemm_mma<DH_>,
                         cudaFuncAttributeMaxDynamicSharedMemorySize, gemm_smem);
    cudaFuncSetAttribute(attn_kernel,
                         cudaFuncAttributeMaxDynamicSharedMemorySize, attn_smem);

    // 0) pack weights + transpose/pack x
    pack_kernel<<<(HQKV * DIM_ + 255) / 256, 256>>>(qkv_w, wq_p, HQKV * DIM_);
    pack_kernel<<<(DIM_ * DH_ + 255) / 256, 256>>>(proj_w, wp_p, DIM_ * DH_);
    transpose_pack<<<dim3(N_ / 32, DIM_ / 32, B_), 256>>>(
        x, xT_p, DIM_, N_, 0, (size_t)B_ * N_ * DIM_);

    // 1) QKV pointwise conv + scale/bias (tensor cores)
    gemm_mma<DIM_><<<dim3(N_ / 128, HQKV / 128, B_), 256, gemm_smem>>>(
        wq_p, xT_p, qkv_p, qkv_scale, qkv_bias, HQKV, N_,
        (size_t)HQKV * DIM_, (size_t)B_ * N_ * DIM_);

    // 2) depthwise 3x3x3 conv on q
    dwconv_kernel<<<(B_ * NH_KD * N_) / 256, 256>>>(dw_w, dw_scale, dw_bias);

    // 2b) pre-split k and v planes
    prep_k<<<B_ * NHEADS, 256>>>();
    prep_v<<<(B_ * NHEADS * VDIM * N_) / 256, 256>>>();

    // 3) fused attention (tensor cores, ldmatrix operands)
    attn_kernel<<<dim3(N_ / 64, NHEADS, B_), 512, attn_smem>>>(attn_bias, bias_idxs);

    // 3b) relu + transpose + pack attention output
    transpose_pack<<<dim3(N_ / 32, DH_ / 32, B_), 256>>>(
        att_p, aT_p, DH_, N_, 1, (size_t)B_ * N_ * DH_);

    // 4) proj GEMM (tensor cores; relu already applied in prep)
    gemm_mma<DH_><<<dim3(N_ / 128, DIM_ / 128, B_), 256, gemm_smem>>>(
        wp_p, aT_p, out, proj_scale, proj_bias, DIM_, N_,
        (size_t)DIM_ * DH_, (size_t)B_ * N_ * DH_);
}

// round 14
// speedup vs baseline: 1.8969x; 1.1413x over previous
#include <cuda_runtime.h>
#include <cuda_bf16.h>

#define B_      32
#define DIM_    256
#define N_      512
#define NHEADS  8
#define KDIM    16
#define NH_KD   128
#define DH_     512
#define HQKV    768
#define VDIM    64

typedef unsigned long long ull;
typedef __nv_bfloat16 bf16;

// ---------------------------------------------------------------------------
// helpers
// ---------------------------------------------------------------------------
__device__ __forceinline__ unsigned bpack(bf16 a, bf16 b) {
    __nv_bfloat162 t = __halves2bfloat162(a, b);
    return *(unsigned*)&t;
}
__device__ __forceinline__ void split2(float x, bf16& hi, bf16& lo) {
    hi = __float2bfloat16_rn(x);
    lo = __float2bfloat16_rn(x - __bfloat162float(hi));
}
__device__ __forceinline__ void mma_bf16(float* c, const unsigned* a, const unsigned* b) {
    asm volatile(
        "mma.sync.aligned.m16n8k16.row.col.f32.bf16.bf16.f32 "
        "{%0,%1,%2,%3}, {%4,%5,%6,%7}, {%8,%9}, {%0,%1,%2,%3};"
        : "+f"(c[0]), "+f"(c[1]), "+f"(c[2]), "+f"(c[3])
        : "r"(a[0]), "r"(a[1]), "r"(a[2]), "r"(a[3]), "r"(b[0]), "r"(b[1]));
}
__device__ __forceinline__ void ldsm4(unsigned* r, const bf16* p) {
    unsigned a = (unsigned)__cvta_generic_to_shared(p);
    asm volatile("ldmatrix.sync.aligned.m8n8.x4.shared.b16 {%0,%1,%2,%3}, [%4];"
                 : "=r"(r[0]), "=r"(r[1]), "=r"(r[2]), "=r"(r[3]) : "r"(a));
}
__device__ __forceinline__ void cp16(void* dst, const void* src) {
    unsigned d = (unsigned)__cvta_generic_to_shared(dst);
    asm volatile("cp.async.cg.shared.global [%0], [%1], 16;" :: "r"(d), "l"(src));
}

// ---------------------------------------------------------------------------
// Scratch (device globals; hi/lo planes stored contiguously: [2][...])
// ---------------------------------------------------------------------------
__device__ float g_qkv[(size_t)B_ * HQKV * N_];     // only q,k channel rows used
__device__ float g_q  [(size_t)B_ * NH_KD * N_];
__device__ bf16  g_wq [(size_t)2 * HQKV * DIM_];          // [m][k] planes
__device__ bf16  g_wp [(size_t)2 * DIM_ * DH_];
__device__ bf16  g_xT [(size_t)2 * B_ * N_ * DIM_];       // [b][n][k] planes
__device__ bf16  g_aT [(size_t)2 * B_ * N_ * DH_];        // relu(att)^T planes
__device__ bf16  g_kp [(size_t)2 * B_ * NHEADS * N_ * KDIM];   // [bh][m][k]
__device__ bf16  g_vp [(size_t)2 * B_ * NHEADS * VDIM * N_];   // [bh][d][m]

#define PSK ((size_t)B_ * NHEADS * N_ * KDIM)
#define PSV ((size_t)B_ * NHEADS * VDIM * N_)
#define PSA ((size_t)B_ * N_ * DH_)

// ---------------------------------------------------------------------------
// prep kernels
// ---------------------------------------------------------------------------
__global__ void pack_kernel(const float* __restrict__ src, bf16* __restrict__ dst, int n)
{
    int i = blockIdx.x * 256 + threadIdx.x;
    if (i < n) {
        bf16 hi, lo; split2(src[i], hi, lo);
        dst[i] = hi; dst[n + i] = lo;
    }
}

// src [b][K][N] fp32 -> dst [b][N][K] bf16 planes
__global__ void transpose_pack(const float* __restrict__ src, bf16* __restrict__ dst,
                               int K, int N, size_t ps)
{
    __shared__ float tile[32][33];
    const int b = blockIdx.z;
    const int k0 = blockIdx.y * 32, n0 = blockIdx.x * 32;
    const int tx = threadIdx.x & 31, ty = threadIdx.x >> 5;
    const float* sb = src + (size_t)b * K * N;
    bf16* db = dst + (size_t)b * N * K;
#pragma unroll
    for (int i = 0; i < 4; i++)
        tile[ty + i * 8][tx] = sb[(size_t)(k0 + ty + i * 8) * N + n0 + tx];
    __syncthreads();
#pragma unroll
    for (int i = 0; i < 4; i++) {
        float v = tile[tx][ty + i * 8];
        bf16 hi, lo; split2(v, hi, lo);
        size_t o = (size_t)(n0 + ty + i * 8) * K + k0 + tx;
        db[o] = hi; db[ps + o] = lo;
    }
}

// k channels -> g_kp [bh][m=512][k=16] planes (transpose via smem)
__global__ void prep_k()
{
    __shared__ unsigned sm[512 * 17];
    const int bh = blockIdx.x;
    const int b = bh >> 3, h = bh & 7;
    const int tid = threadIdx.x;
    const float* src = g_qkv + ((size_t)b * HQKV + NH_KD + h * KDIM) * N_;
#pragma unroll
    for (int i = 0; i < 32; i++) {
        int e = tid + i * 256;
        int k = e >> 9, n = e & 511;
        bf16 hi, lo; split2(src[(size_t)k * N_ + n], hi, lo);
        sm[n * 17 + k] = bpack(hi, lo);
    }
    __syncthreads();
    bf16* dst = g_kp + (size_t)bh * N_ * KDIM;
#pragma unroll
    for (int i = 0; i < 32; i++) {
        int e = tid + i * 256;
        unsigned u = sm[(e >> 4) * 17 + (e & 15)];
        unsigned short hs = (unsigned short)(u & 0xffff), ls = (unsigned short)(u >> 16);
        dst[e] = *(bf16*)&hs; dst[PSK + e] = *(bf16*)&ls;
    }
}

// ---------------------------------------------------------------------------
// Tensor-core CBN GEMM (ldmatrix + cp.async), with optional fused v-plane
// epilogue: tiles with m0 >= vbase write split bf16 planes into vpl
// ([bh][d][m] layout) instead of fp32 C.
// ---------------------------------------------------------------------------
template <int K>
__global__ __launch_bounds__(256, 2)
void gemm_mma(const bf16* __restrict__ Apk, const bf16* __restrict__ Bpk,
              float* __restrict__ Cg, const float* __restrict__ scale,
              const float* __restrict__ bias, int M, int N,
              size_t aps, size_t bps, bf16* vpl, int vbase, size_t vps)
{
    extern __shared__ bf16 smh[];
    const int b = blockIdx.z;
    const bf16* Bb = Bpk + (size_t)b * N * K;
    float* Cb = Cg + (size_t)b * M * N;
    const int m0 = blockIdx.y * 128, n0 = blockIdx.x * 128;
    const int tid = threadIdx.x, warp = tid >> 5, lane = tid & 31;
    const int r = lane >> 2, c2 = (lane & 3) * 2;
    const int wm = warp >> 1, wn = warp & 1;
    const int lrow = lane & 15, lcol = (lane >> 4) * 8;

    float acc[2][8][4];
#pragma unroll
    for (int i = 0; i < 2; i++)
#pragma unroll
        for (int j = 0; j < 8; j++)
#pragma unroll
            for (int q = 0; q < 4; q++) acc[i][j][q] = 0.f;

    auto issue = [&](int t) {
        const int k0 = t * 32;
        bf16* sb = smh + (t & 1) * 20480;
#pragma unroll
        for (int i = 0; i < 8; i++) {
            int e = tid + i * 256;
            int plane = e >> 9, idx = e & 511;
            int row = idx >> 2, seg = (idx & 3) * 8;
            const bf16* src;
            bf16* dst;
            if (plane == 0)      { src = Apk + (size_t)(m0 + row) * K + k0 + seg;       dst = sb + row * 40 + seg; }
            else if (plane == 1) { src = Apk + aps + (size_t)(m0 + row) * K + k0 + seg; dst = sb + 5120 + row * 40 + seg; }
            else if (plane == 2) { src = Bb + (size_t)(n0 + row) * K + k0 + seg;        dst = sb + 10240 + row * 40 + seg; }
            else                 { src = Bb + bps + (size_t)(n0 + row) * K + k0 + seg;  dst = sb + 15360 + row * 40 + seg; }
            cp16(dst, src);
        }
        asm volatile("cp.async.commit_group;");
    };

    issue(0);
    constexpr int T = K / 32;
#pragma unroll 1
    for (int t = 0; t < T; t++) {
        if (t + 1 < T) {
            issue(t + 1);
            asm volatile("cp.async.wait_group 1;");
        } else {
            asm volatile("cp.async.wait_group 0;");
        }
        __syncthreads();

        const bf16* As = smh + (t & 1) * 20480;
        const bf16* Bs = As + 10240;
#pragma unroll
        for (int ks = 0; ks < 32; ks += 16) {
            unsigned ah[2][4], al[2][4];
#pragma unroll
            for (int mt = 0; mt < 2; mt++) {
                const int row = wm * 32 + mt * 16 + lrow;
                ldsm4(ah[mt], As + row * 40 + ks + lcol);
                ldsm4(al[mt], As + 5120 + row * 40 + ks + lcol);
            }
#pragma unroll
            for (int ng = 0; ng < 4; ng++) {
                const int row = wn * 64 + ng * 16 + lrow;
                unsigned h4[4], l4[4];
                ldsm4(h4, Bs + row * 40 + ks + lcol);
                ldsm4(l4, Bs + 5120 + row * 40 + ks + lcol);
#pragma unroll
                for (int sub = 0; sub < 2; sub++) {
                    unsigned bh[2]  = {h4[sub], h4[sub + 2]};
                    unsigned bl2[2] = {l4[sub], l4[sub + 2]};
                    const int nt = ng * 2 + sub;
#pragma unroll
                    for (int mt = 0; mt < 2; mt++) {
                        mma_bf16(acc[mt][nt], ah[mt], bh);
                        mma_bf16(acc[mt][nt], al[mt], bh);
                        mma_bf16(acc[mt][nt], ah[mt], bl2);
                    }
                }
            }
        }
        __syncthreads();
    }

    if (vpl != nullptr && m0 >= vbase) {
        // fused: scale/bias then split bf16 planes into vpl [bh][d][m]
#pragma unroll
        for (int mt = 0; mt < 2; mt++) {
            const int mr0 = m0 + wm * 32 + mt * 16 + r;
            const int mr1 = mr0 + 8;
            const float s0 = scale[mr0], b0 = bias[mr0];
            const float s1 = scale[mr1], b1 = bias[mr1];
            const int vo0 = mr0 - vbase, vo1 = mr1 - vbase;
            bf16* d0 = vpl + ((size_t)(b * 8 + (vo0 >> 6)) * VDIM + (vo0 & 63)) * N_;
            bf16* d1 = vpl + ((size_t)(b * 8 + (vo1 >> 6)) * VDIM + (vo1 & 63)) * N_;
#pragma unroll
            for (int nt = 0; nt < 8; nt++) {
                const int col = n0 + wn * 64 + nt * 8 + c2;
                float v0 = fmaf(acc[mt][nt][0], s0, b0);
                float v1 = fmaf(acc[mt][nt][1], s0, b0);
                float v2 = fmaf(acc[mt][nt][2], s1, b1);
                float v3 = fmaf(acc[mt][nt][3], s1, b1);
                bf16 h0, l0, h1, l1;
                split2(v0, h0, l0); split2(v1, h1, l1);
                *(unsigned*)&d0[col]       = bpack(h0, h1);
                *(unsigned*)&d0[vps + col] = bpack(l0, l1);
                split2(v2, h0, l0); split2(v3, h1, l1);
                *(unsigned*)&d1[col]       = bpack(h0, h1);
                *(unsigned*)&d1[vps + col] = bpack(l0, l1);
            }
        }
    } else {
#pragma unroll
        for (int mt = 0; mt < 2; mt++) {
            const int mr0 = m0 + wm * 32 + mt * 16 + r;
            const int mr1 = mr0 + 8;
            const float s0 = scale[mr0], b0 = bias[mr0];
            const float s1 = scale[mr1], b1 = bias[mr1];
#pragma unroll
            for (int nt = 0; nt < 8; nt++) {
                const int col = n0 + wn * 64 + nt * 8 + c2;
                float2 o0, o1;
                o0.x = fmaf(acc[mt][nt][0], s0, b0);
                o0.y = fmaf(acc[mt][nt][1], s0, b0);
                o1.x = fmaf(acc[mt][nt][2], s1, b1);
                o1.y = fmaf(acc[mt][nt][3], s1, b1);
                *(float2*)&Cb[(size_t)mr0 * N + col] = o0;
                *(float2*)&Cb[(size_t)mr1 * N + col] = o1;
            }
        }
    }
}

// ---------------------------------------------------------------------------
// Depthwise 3x3x3 conv on q channels, pad=1, then scale/bias.
// ---------------------------------------------------------------------------
__global__ __launch_bounds__(256)
void dwconv_kernel(const float* __restrict__ w,
                   const float* __restrict__ scale,
                   const float* __restrict__ bias)
{
    int idx = blockIdx.x * 256 + threadIdx.x;
    int n = idx & 511;
    int c = (idx >> 9) & 127;
    int b = idx >> 16;
    int xx = n & 7, yy = (n >> 3) & 7, zz = n >> 6;

    const float* src = g_qkv + ((size_t)b * HQKV + c) * N_;
    const float* wc = w + c * 27;
    float acc = 0.f;
#pragma unroll
    for (int dz = 0; dz < 3; dz++) {
        int z = zz + dz - 1;
        if (z < 0 || z > 7) continue;
#pragma unroll
        for (int dy = 0; dy < 3; dy++) {
            int y = yy + dy - 1;
            if (y < 0 || y > 7) continue;
#pragma unroll
            for (int dx = 0; dx < 3; dx++) {
                int x = xx + dx - 1;
                if (x < 0 || x > 7) continue;
                acc = fmaf(src[z * 64 + y * 8 + x], wc[dz * 9 + dy * 3 + dx], acc);
            }
        }
    }
    g_q[((size_t)b * NH_KD + c) * N_ + n] = fmaf(acc, scale[c], bias[c]);
}

// ---------------------------------------------------------------------------
// Fused attention per (b, h, 32-row n-tile), 256 threads (8 warps), 2 CTA/SM.
// K streamed per-64-m-tile (double-buffered) in phase 1; V double-buffered in
// phase 3. Epilogue writes relu+split planes directly to g_aT [b][n][dh].
// SMEM (halves): Shi@0 [32][520], Slo@16640, qhi@33280 [32][24], qlo@34048,
// ab fp32[512]@34816(half units), kv scratch @35840: k bufs 2x3072,
// v bufs 2x9216. Total 54272 halves = 108544 B.
// ---------------------------------------------------------------------------
#define SH  0
#define SL  16640
#define QH  33280
#define QL  34048
#define ABO 34816
#define KV  35840

__global__ __launch_bounds__(256, 2)
void attn_kernel(const float* __restrict__ attn_biases,
                 const int* __restrict__ bias_idxs)
{
    extern __shared__ bf16 smh[];
    float* ab = (float*)(smh + ABO);

    const int b  = blockIdx.z, h = blockIdx.y;
    const int bh = b * 8 + h;
    const int n0 = blockIdx.x * 32;
    const int tid = threadIdx.x;
    const int warp = tid >> 5, lane = tid & 31;
    const int r  = lane >> 2, c2 = (lane & 3) * 2;
    const int lrow = lane & 15, lcol = (lane >> 4) * 8;
    const int wb = warp & 1;          // n band (16 rows)
    const int wq = warp >> 1;         // m/d quarter (16 cols)

    const float* qb = g_q + ((size_t)b * NH_KD + h * KDIM) * N_;
    const bf16* khg = g_kp + (size_t)bh * N_ * KDIM;
    const bf16* vhg = g_vp + (size_t)bh * VDIM * N_;

    auto issue_k = [&](int t) {
        bf16* dst = smh + KV + (t & 1) * 3072;
        int e = tid;                       // 256 chunks: 2 planes x 64 rows x 2
        int plane = e >> 7, idx = e & 127;
        int row = idx >> 1, seg = (idx & 1) * 8;
        const bf16* src = (plane ? khg + PSK : khg) + (size_t)(t * 64 + row) * KDIM + seg;
        cp16(dst + plane * 1536 + row * 24 + seg, src);
        asm volatile("cp.async.commit_group;");
    };
    auto issue_v = [&](int t) {
        bf16* dst = smh + KV + (t & 1) * 9216;
#pragma unroll
        for (int i = 0; i < 4; i++) {
            int e = tid + i * 256;
            int plane = e >> 9, idx = e & 511;
            int row = idx >> 3, seg = (idx & 7) * 8;
            const bf16* src = (plane ? vhg + PSV : vhg) + (size_t)row * N_ + t * 64 + seg;
            cp16(dst + plane * 4608 + row * 72 + seg, src);
        }
        asm volatile("cp.async.commit_group;");
    };

    // stage q split [32 n][16 k] (512 elems, 2 per thread)  **FIXED**
#pragma unroll
    for (int i = 0; i < 2; i++) {
        int e = tid + i * 256;
        int k = e >> 5, n = e & 31;
        bf16 hi, lo; split2(qb[(size_t)k * N_ + n0 + n], hi, lo);
        smh[QH + n * 24 + k] = hi;
        smh[QL + n * 24 + k] = lo;
    }
    ab[tid] = attn_biases[h * N_ + tid];
    ab[tid + 256] = attn_biases[h * N_ + tid + 256];

    issue_k(0);
    __syncthreads();

    // q fragment (held across phase 1)
    unsigned qh4[4], ql4[4];
    ldsm4(qh4, smh + QH + (wb * 16 + lrow) * 24 + lcol);
    ldsm4(ql4, smh + QL + (wb * 16 + lrow) * 24 + lcol);

    // ---- Phase 1: S = q^T k * 0.25 + bias over 8 m-tiles of 64 ----
#pragma unroll 1
    for (int t = 0; t < 8; t++) {
        if (t + 1 < 8) {
            issue_k(t + 1);
            asm volatile("cp.async.wait_group 1;");
        } else {
            asm volatile("cp.async.wait_group 0;");
        }
        __syncthreads();

        const bf16* kb = smh + KV + (t & 1) * 3072;
        unsigned kh4[4], kl4[4];
        ldsm4(kh4, kb + (wq * 16 + lrow) * 24 + lcol);
        ldsm4(kl4, kb + 1536 + (wq * 16 + lrow) * 24 + lcol);
#pragma unroll
        for (int sub = 0; sub < 2; sub++) {
            unsigned bh2[2]  = {kh4[sub], kh4[sub + 2]};
            unsigned bl2[2] = {kl4[sub], kl4[sub + 2]};
            float c[4] = {0.f, 0.f, 0.f, 0.f};
            mma_bf16(c, qh4, bh2);
            mma_bf16(c, ql4, bh2);
            mma_bf16(c, qh4, bl2);

            const int nr0 = wb * 16 + r, nr1 = nr0 + 8;
            const int mc = t * 64 + wq * 16 + sub * 8 + c2;
            int2 i0 = *(const int2*)&bias_idxs[(size_t)(n0 + nr0) * N_ + mc];
            int2 i1 = *(const int2*)&bias_idxs[(size_t)(n0 + nr1) * N_ + mc];
            float o0 = fmaf(c[0], 0.25f, ab[i0.x]);
            float o1 = fmaf(c[1], 0.25f, ab[i0.y]);
            float o2 = fmaf(c[2], 0.25f, ab[i1.x]);
            float o3 = fmaf(c[3], 0.25f, ab[i1.y]);
            bf16 h0, l0, h1, l1;
            split2(o0, h0, l0); split2(o1, h1, l1);
            *(unsigned*)&smh[SH + nr0 * 520 + mc] = bpack(h0, h1);
            *(unsigned*)&smh[SL + nr0 * 520 + mc] = bpack(l0, l1);
            split2(o2, h0, l0); split2(o3, h1, l1);
            *(unsigned*)&smh[SH + nr1 * 520 + mc] = bpack(h0, h1);
            *(unsigned*)&smh[SL + nr1 * 520 + mc] = bpack(l0, l1);
        }
        __syncthreads();
    }

    // ---- Phase 2: softmax (4 rows per warp) ----
    for (int rr = warp; rr < 32; rr += 8) {
        const int base = rr * 520;
        float e[16];
        float mx = -1e30f;
#pragma unroll
        for (int j = 0; j < 16; j++) {
            int o = base + lane + j * 32;
            e[j] = __bfloat162float(smh[SH + o]) + __bfloat162float(smh[SL + o]);
            mx = fmaxf(mx, e[j]);
        }
#pragma unroll
        for (int off = 16; off; off >>= 1)
            mx = fmaxf(mx, __shfl_xor_sync(0xffffffffu, mx, off));
        float sum = 0.f;
#pragma unroll
        for (int j = 0; j < 16; j++) { e[j] = __expf(e[j] - mx); sum += e[j]; }
#pragma unroll
        for (int off = 16; off; off >>= 1)
            sum += __shfl_xor_sync(0xffffffffu, sum, off);
        float inv = 1.f / sum;
#pragma unroll
        for (int j = 0; j < 16; j++) {
            bf16 hi, lo; split2(e[j] * inv, hi, lo);
            int o = base + lane + j * 32;
            smh[SH + o] = hi; smh[SL + o] = lo;
        }
    }

    // ---- Phase 3: O[n][d] = P @ V^T over 8 m-tiles of 64 ----
    float oacc[2][4];
#pragma unroll
    for (int i = 0; i < 2; i++)
#pragma unroll
        for (int j = 0; j < 4; j++) oacc[i][j] = 0.f;

    issue_v(0);
#pragma unroll 1
    for (int mt = 0; mt < 8; mt++) {
        if (mt + 1 < 8) {
            issue_v(mt + 1);
            asm volatile("cp.async.wait_group 1;");
        } else {
            asm volatile("cp.async.wait_group 0;");
        }
        __syncthreads();

        const bf16* vb = smh + KV + (mt & 1) * 9216;
#pragma unroll
        for (int ks = 0; ks < 4; ks++) {
            unsigned ph[4], pl[4];
            ldsm4(ph, smh + SH + (wb * 16 + lrow) * 520 + mt * 64 + ks * 16 + lcol);
            ldsm4(pl, smh + SL + (wb * 16 + lrow) * 520 + mt * 64 + ks * 16 + lcol);
            unsigned vh4[4], vl4[4];
            ldsm4(vh4, vb + (wq * 16 + lrow) * 72 + ks * 16 + lcol);
            ldsm4(vl4, vb + 4608 + (wq * 16 + lrow) * 72 + ks * 16 + lcol);
#pragma unroll
            for (int dt = 0; dt < 2; dt++) {
                unsigned bh2[2]  = {vh4[dt], vh4[dt + 2]};
                unsigned bl2[2] = {vl4[dt], vl4[dt + 2]};
                mma_bf16(oacc[dt], ph, bh2);
                mma_bf16(oacc[dt], pl, bh2);
                mma_bf16(oacc[dt], ph, bl2);
            }
        }
        __syncthreads();
    }

    // ---- epilogue: relu + split + store directly to g_aT [b][n][dh] planes ----
    bf16* aT = g_aT + (size_t)b * N_ * DH_;
#pragma unroll
    for (int dt = 0; dt < 2; dt++) {
        const int col = h * 64 + wq * 16 + dt * 8 + c2;
        const int nr0 = n0 + wb * 16 + r, nr1 = nr0 + 8;
        float v0 = fmaxf(oacc[dt][0], 0.f), v1 = fmaxf(oacc[dt][1], 0.f);
        float v2 = fmaxf(oacc[dt][2], 0.f), v3 = fmaxf(oacc[dt][3], 0.f);
        bf16 h0, l0, h1, l1;
        split2(v0, h0, l0); split2(v1, h1, l1);
        *(unsigned*)&aT[(size_t)nr0 * DH_ + col]       = bpack(h0, h1);
        *(unsigned*)&aT[PSA + (size_t)nr0 * DH_ + col] = bpack(l0, l1);
        split2(v2, h0, l0); split2(v3, h1, l1);
        *(unsigned*)&aT[(size_t)nr1 * DH_ + col]       = bpack(h0, h1);
        *(unsigned*)&aT[PSA + (size_t)nr1 * DH_ + col] = bpack(l0, l1);
    }
}

// ---------------------------------------------------------------------------
extern "C" void kernel_launch(void* const* d_in, const int* in_sizes, int n_in,
                              void* d_out, int out_size)
{
    const float* x          = (const float*)d_in[0];
    const float* qkv_w      = (const float*)d_in[1];
    const float* qkv_scale  = (const float*)d_in[2];
    const float* qkv_bias   = (const float*)d_in[3];
    const float* dw_w       = (const float*)d_in[4];
    const float* dw_scale   = (const float*)d_in[5];
    const float* dw_bias    = (const float*)d_in[6];
    const float* attn_bias  = (const float*)d_in[7];
    const float* proj_w     = (const float*)d_in[8];
    const float* proj_scale = (const float*)d_in[9];
    const float* proj_bias  = (const float*)d_in[10];
    const int*   bias_idxs  = (const int*)d_in[11];
    float* out = (float*)d_out;

    float* qkv_p;
    bf16 *wq_p, *wp_p, *xT_p, *aT_p, *vp_p;
    cudaGetSymbolAddress((void**)&qkv_p, g_qkv);
    cudaGetSymbolAddress((void**)&wq_p, g_wq);
    cudaGetSymbolAddress((void**)&wp_p, g_wp);
    cudaGetSymbolAddress((void**)&xT_p, g_xT);
    cudaGetSymbolAddress((void**)&aT_p, g_aT);
    cudaGetSymbolAddress((void**)&vp_p, g_vp);

    const int gemm_smem = 81920;
    const int attn_smem = 108544;
    cudaFuncSetAttribute(gemm_mma<DIM_>,
                         cudaFuncAttributeMaxDynamicSharedMemorySize, gemm_smem);
    cudaFuncSetAttribute(gemm_mma<DH_>,
                         cudaFuncAttributeMaxDynamicSharedMemorySize, gemm_smem);
    cudaFuncSetAttribute(attn_kernel,
                         cudaFuncAttributeMaxDynamicSharedMemorySize, attn_smem);

    // 0) pack weights + transpose/pack x
    pack_kernel<<<(HQKV * DIM_ + 255) / 256, 256>>>(qkv_w, wq_p, HQKV * DIM_);
    pack_kernel<<<(DIM_ * DH_ + 255) / 256, 256>>>(proj_w, wp_p, DIM_ * DH_);
    transpose_pack<<<dim3(N_ / 32, DIM_ / 32, B_), 256>>>(
        x, xT_p, DIM_, N_, (size_t)B_ * N_ * DIM_);

    // 1) QKV GEMM: q,k rows -> fp32 g_qkv; v rows -> split planes g_vp (fused)
    gemm_mma<DIM_><<<dim3(N_ / 128, HQKV / 128, B_), 256, gemm_smem>>>(
        wq_p, xT_p, qkv_p, qkv_scale, qkv_bias, HQKV, N_,
        (size_t)HQKV * DIM_, (size_t)B_ * N_ * DIM_, vp_p, 2 * NH_KD, PSV);

    // 2) depthwise 3x3x3 conv on q + k split planes
    dwconv_kernel<<<(B_ * NH_KD * N_) / 256, 256>>>(dw_w, dw_scale, dw_bias);
    prep_k<<<B_ * NHEADS, 256>>>();

    // 3) fused attention (2 CTAs/SM; writes relu+split aT directly)
    attn_kernel<<<dim3(N_ / 32, NHEADS, B_), 256, attn_smem>>>(attn_bias, bias_idxs);

    // 4) proj GEMM (reads aT planes)
    gemm_mma<DH_><<<dim3(N_ / 128, DIM_ / 128, B_), 256, gemm_smem>>>(
        wp_p, aT_p, out, proj_scale, proj_bias, DIM_, N_,
        (size_t)DIM_ * DH_, (size_t)B_ * N_ * DH_, (bf16*)nullptr, 1 << 30, 0);
}

// round 16
// speedup vs baseline: 1.9151x; 1.0096x over previous
#include <cuda_runtime.h>
#include <cuda_bf16.h>

#define B_      32
#define DIM_    256
#define N_      512
#define NHEADS  8
#define KDIM    16
#define NH_KD   128
#define DH_     512
#define HQKV    768
#define VDIM    64

typedef unsigned long long ull;
typedef __nv_bfloat16 bf16;

// ---------------------------------------------------------------------------
// helpers
// ---------------------------------------------------------------------------
__device__ __forceinline__ unsigned bpack(bf16 a, bf16 b) {
    __nv_bfloat162 t = __halves2bfloat162(a, b);
    return *(unsigned*)&t;
}
__device__ __forceinline__ void split2(float x, bf16& hi, bf16& lo) {
    hi = __float2bfloat16_rn(x);
    lo = __float2bfloat16_rn(x - __bfloat162float(hi));
}
__device__ __forceinline__ void mma_bf16(float* c, const unsigned* a, const unsigned* b) {
    asm volatile(
        "mma.sync.aligned.m16n8k16.row.col.f32.bf16.bf16.f32 "
        "{%0,%1,%2,%3}, {%4,%5,%6,%7}, {%8,%9}, {%0,%1,%2,%3};"
        : "+f"(c[0]), "+f"(c[1]), "+f"(c[2]), "+f"(c[3])
        : "r"(a[0]), "r"(a[1]), "r"(a[2]), "r"(a[3]), "r"(b[0]), "r"(b[1]));
}
__device__ __forceinline__ void ldsm4(unsigned* r, const bf16* p) {
    unsigned a = (unsigned)__cvta_generic_to_shared(p);
    asm volatile("ldmatrix.sync.aligned.m8n8.x4.shared.b16 {%0,%1,%2,%3}, [%4];"
                 : "=r"(r[0]), "=r"(r[1]), "=r"(r[2]), "=r"(r[3]) : "r"(a));
}
__device__ __forceinline__ void cp16(void* dst, const void* src) {
    unsigned d = (unsigned)__cvta_generic_to_shared(dst);
    asm volatile("cp.async.cg.shared.global [%0], [%1], 16;" :: "r"(d), "l"(src));
}

// ---------------------------------------------------------------------------
// Scratch (device globals; hi/lo planes stored contiguously: [2][...])
// ---------------------------------------------------------------------------
__device__ float g_qkv[(size_t)B_ * HQKV * N_];     // only q channel rows used
__device__ float g_q  [(size_t)B_ * NH_KD * N_];
__device__ bf16  g_wq [(size_t)2 * HQKV * DIM_];          // [m][k] planes
__device__ bf16  g_wp [(size_t)2 * DIM_ * DH_];
__device__ bf16  g_xT [(size_t)2 * B_ * N_ * DIM_];       // [b][n][k] planes
__device__ bf16  g_aT [(size_t)2 * B_ * N_ * DH_];        // relu(att)^T planes
__device__ bf16  g_kp [(size_t)2 * B_ * NHEADS * N_ * KDIM];   // [bh][m][k]
__device__ bf16  g_vp [(size_t)2 * B_ * NHEADS * VDIM * N_];   // [bh][d][m]

#define PSK ((size_t)B_ * NHEADS * N_ * KDIM)
#define PSV ((size_t)B_ * NHEADS * VDIM * N_)
#define PSA ((size_t)B_ * N_ * DH_)

// ---------------------------------------------------------------------------
// prep kernels
// ---------------------------------------------------------------------------
__global__ void pack_kernel(const float* __restrict__ src, bf16* __restrict__ dst, int n)
{
    int i = blockIdx.x * 256 + threadIdx.x;
    if (i < n) {
        bf16 hi, lo; split2(src[i], hi, lo);
        dst[i] = hi; dst[n + i] = lo;
    }
}

// src [b][K][N] fp32 -> dst [b][N][K] bf16 planes
__global__ void transpose_pack(const float* __restrict__ src, bf16* __restrict__ dst,
                               int K, int N, size_t ps)
{
    __shared__ float tile[32][33];
    const int b = blockIdx.z;
    const int k0 = blockIdx.y * 32, n0 = blockIdx.x * 32;
    const int tx = threadIdx.x & 31, ty = threadIdx.x >> 5;
    const float* sb = src + (size_t)b * K * N;
    bf16* db = dst + (size_t)b * N * K;
#pragma unroll
    for (int i = 0; i < 4; i++)
        tile[ty + i * 8][tx] = sb[(size_t)(k0 + ty + i * 8) * N + n0 + tx];
    __syncthreads();
#pragma unroll
    for (int i = 0; i < 4; i++) {
        float v = tile[tx][ty + i * 8];
        bf16 hi, lo; split2(v, hi, lo);
        size_t o = (size_t)(n0 + ty + i * 8) * K + k0 + tx;
        db[o] = hi; db[ps + o] = lo;
    }
}

// ---------------------------------------------------------------------------
// Tensor-core CBN GEMM (ldmatrix + cp.async), with fused epilogues:
//   m0 == NH_KD (k channels, qkv only): split planes -> kpl [bh][token][chan]
//   m0 >= vbase (v channels, qkv only): split planes -> vpl [bh][d][m]
//   otherwise: fp32 C with scale/bias
// ---------------------------------------------------------------------------
template <int K>
__global__ __launch_bounds__(256, 2)
void gemm_mma(const bf16* __restrict__ Apk, const bf16* __restrict__ Bpk,
              float* __restrict__ Cg, const float* __restrict__ scale,
              const float* __restrict__ bias, int M, int N,
              size_t aps, size_t bps,
              bf16* vpl, int vbase, size_t vps,
              bf16* kpl, size_t kps)
{
    extern __shared__ bf16 smh[];
    const int b = blockIdx.z;
    const bf16* Bb = Bpk + (size_t)b * N * K;
    float* Cb = Cg + (size_t)b * M * N;
    const int m0 = blockIdx.y * 128, n0 = blockIdx.x * 128;
    const int tid = threadIdx.x, warp = tid >> 5, lane = tid & 31;
    const int r = lane >> 2, c2 = (lane & 3) * 2;
    const int wm = warp >> 1, wn = warp & 1;
    const int lrow = lane & 15, lcol = (lane >> 4) * 8;

    float acc[2][8][4];
#pragma unroll
    for (int i = 0; i < 2; i++)
#pragma unroll
        for (int j = 0; j < 8; j++)
#pragma unroll
            for (int q = 0; q < 4; q++) acc[i][j][q] = 0.f;

    auto issue = [&](int t) {
        const int k0 = t * 32;
        bf16* sb = smh + (t & 1) * 20480;
#pragma unroll
        for (int i = 0; i < 8; i++) {
            int e = tid + i * 256;
            int plane = e >> 9, idx = e & 511;
            int row = idx >> 2, seg = (idx & 3) * 8;
            const bf16* src;
            bf16* dst;
            if (plane == 0)      { src = Apk + (size_t)(m0 + row) * K + k0 + seg;       dst = sb + row * 40 + seg; }
            else if (plane == 1) { src = Apk + aps + (size_t)(m0 + row) * K + k0 + seg; dst = sb + 5120 + row * 40 + seg; }
            else if (plane == 2) { src = Bb + (size_t)(n0 + row) * K + k0 + seg;        dst = sb + 10240 + row * 40 + seg; }
            else                 { src = Bb + bps + (size_t)(n0 + row) * K + k0 + seg;  dst = sb + 15360 + row * 40 + seg; }
            cp16(dst, src);
        }
        asm volatile("cp.async.commit_group;");
    };

    issue(0);
    constexpr int T = K / 32;
#pragma unroll 1
    for (int t = 0; t < T; t++) {
        if (t + 1 < T) {
            issue(t + 1);
            asm volatile("cp.async.wait_group 1;");
        } else {
            asm volatile("cp.async.wait_group 0;");
        }
        __syncthreads();

        const bf16* As = smh + (t & 1) * 20480;
        const bf16* Bs = As + 10240;
#pragma unroll
        for (int ks = 0; ks < 32; ks += 16) {
            unsigned ah[2][4], al[2][4];
#pragma unroll
            for (int mt = 0; mt < 2; mt++) {
                const int row = wm * 32 + mt * 16 + lrow;
                ldsm4(ah[mt], As + row * 40 + ks + lcol);
                ldsm4(al[mt], As + 5120 + row * 40 + ks + lcol);
            }
#pragma unroll
            for (int ng = 0; ng < 4; ng++) {
                const int row = wn * 64 + ng * 16 + lrow;
                unsigned h4[4], l4[4];
                ldsm4(h4, Bs + row * 40 + ks + lcol);
                ldsm4(l4, Bs + 5120 + row * 40 + ks + lcol);
#pragma unroll
                for (int sub = 0; sub < 2; sub++) {
                    unsigned bh[2]  = {h4[sub], h4[sub + 2]};
                    unsigned bl2[2] = {l4[sub], l4[sub + 2]};
                    const int nt = ng * 2 + sub;
#pragma unroll
                    for (int mt = 0; mt < 2; mt++) {
                        mma_bf16(acc[mt][nt], ah[mt], bh);
                        mma_bf16(acc[mt][nt], al[mt], bh);
                        mma_bf16(acc[mt][nt], ah[mt], bl2);
                    }
                }
            }
        }
        __syncthreads();
    }

    if (kpl != nullptr && m0 == NH_KD) {
        // fused k-channel epilogue: scale/bias -> split planes, [bh][token][chan]
#pragma unroll
        for (int mt = 0; mt < 2; mt++) {
            const int mr0 = m0 + wm * 32 + mt * 16 + r;
            const int mr1 = mr0 + 8;
            const float s0 = scale[mr0], b0 = bias[mr0];
            const float s1 = scale[mr1], b1 = bias[mr1];
            const int c0 = mr0 - NH_KD, c1 = mr1 - NH_KD;
            bf16* kb0 = kpl + ((size_t)(b * 8 + (c0 >> 4)) * N_) * KDIM + (c0 & 15);
            bf16* kb1 = kpl + ((size_t)(b * 8 + (c1 >> 4)) * N_) * KDIM + (c1 & 15);
#pragma unroll
            for (int nt = 0; nt < 8; nt++) {
                const int col = n0 + wn * 64 + nt * 8 + c2;
                float v0 = fmaf(acc[mt][nt][0], s0, b0);
                float v1 = fmaf(acc[mt][nt][1], s0, b0);
                float v2 = fmaf(acc[mt][nt][2], s1, b1);
                float v3 = fmaf(acc[mt][nt][3], s1, b1);
                bf16 h0, l0, h1, l1;
                split2(v0, h0, l0); split2(v1, h1, l1);
                kb0[(size_t)col * KDIM]            = h0;
                kb0[(size_t)(col + 1) * KDIM]      = h1;
                kb0[kps + (size_t)col * KDIM]       = l0;
                kb0[kps + (size_t)(col + 1) * KDIM] = l1;
                split2(v2, h0, l0); split2(v3, h1, l1);
                kb1[(size_t)col * KDIM]            = h0;
                kb1[(size_t)(col + 1) * KDIM]      = h1;
                kb1[kps + (size_t)col * KDIM]       = l0;
                kb1[kps + (size_t)(col + 1) * KDIM] = l1;
            }
        }
    } else if (vpl != nullptr && m0 >= vbase) {
        // fused v-channel epilogue: scale/bias -> split planes, [bh][d][m]
#pragma unroll
        for (int mt = 0; mt < 2; mt++) {
            const int mr0 = m0 + wm * 32 + mt * 16 + r;
            const int mr1 = mr0 + 8;
            const float s0 = scale[mr0], b0 = bias[mr0];
            const float s1 = scale[mr1], b1 = bias[mr1];
            const int vo0 = mr0 - vbase, vo1 = mr1 - vbase;
            bf16* d0 = vpl + ((size_t)(b * 8 + (vo0 >> 6)) * VDIM + (vo0 & 63)) * N_;
            bf16* d1 = vpl + ((size_t)(b * 8 + (vo1 >> 6)) * VDIM + (vo1 & 63)) * N_;
#pragma unroll
            for (int nt = 0; nt < 8; nt++) {
                const int col = n0 + wn * 64 + nt * 8 + c2;
                float v0 = fmaf(acc[mt][nt][0], s0, b0);
                float v1 = fmaf(acc[mt][nt][1], s0, b0);
                float v2 = fmaf(acc[mt][nt][2], s1, b1);
                float v3 = fmaf(acc[mt][nt][3], s1, b1);
                bf16 h0, l0, h1, l1;
                split2(v0, h0, l0); split2(v1, h1, l1);
                *(unsigned*)&d0[col]       = bpack(h0, h1);
                *(unsigned*)&d0[vps + col] = bpack(l0, l1);
                split2(v2, h0, l0); split2(v3, h1, l1);
                *(unsigned*)&d1[col]       = bpack(h0, h1);
                *(unsigned*)&d1[vps + col] = bpack(l0, l1);
            }
        }
    } else {
#pragma unroll
        for (int mt = 0; mt < 2; mt++) {
            const int mr0 = m0 + wm * 32 + mt * 16 + r;
            const int mr1 = mr0 + 8;
            const float s0 = scale[mr0], b0 = bias[mr0];
            const float s1 = scale[mr1], b1 = bias[mr1];
#pragma unroll
            for (int nt = 0; nt < 8; nt++) {
                const int col = n0 + wn * 64 + nt * 8 + c2;
                float2 o0, o1;
                o0.x = fmaf(acc[mt][nt][0], s0, b0);
                o0.y = fmaf(acc[mt][nt][1], s0, b0);
                o1.x = fmaf(acc[mt][nt][2], s1, b1);
                o1.y = fmaf(acc[mt][nt][3], s1, b1);
                *(float2*)&Cb[(size_t)mr0 * N + col] = o0;
                *(float2*)&Cb[(size_t)mr1 * N + col] = o1;
            }
        }
    }
}

// ---------------------------------------------------------------------------
// Depthwise 3x3x3 conv on q channels, pad=1, then scale/bias.
// ---------------------------------------------------------------------------
__global__ __launch_bounds__(256)
void dwconv_kernel(const float* __restrict__ w,
                   const float* __restrict__ scale,
                   const float* __restrict__ bias)
{
    int idx = blockIdx.x * 256 + threadIdx.x;
    int n = idx & 511;
    int c = (idx >> 9) & 127;
    int b = idx >> 16;
    int xx = n & 7, yy = (n >> 3) & 7, zz = n >> 6;

    const float* src = g_qkv + ((size_t)b * HQKV + c) * N_;
    const float* wc = w + c * 27;
    float acc = 0.f;
#pragma unroll
    for (int dz = 0; dz < 3; dz++) {
        int z = zz + dz - 1;
        if (z < 0 || z > 7) continue;
#pragma unroll
        for (int dy = 0; dy < 3; dy++) {
            int y = yy + dy - 1;
            if (y < 0 || y > 7) continue;
#pragma unroll
            for (int dx = 0; dx < 3; dx++) {
                int x = xx + dx - 1;
                if (x < 0 || x > 7) continue;
                acc = fmaf(src[z * 64 + y * 8 + x], wc[dz * 9 + dy * 3 + dx], acc);
            }
        }
    }
    g_q[((size_t)b * NH_KD + c) * N_ + n] = fmaf(acc, scale[c], bias[c]);
}

// ---------------------------------------------------------------------------
// Fused attention per (b, h, 32-row n-tile), 256 threads (8 warps), 2 CTA/SM.
// (unchanged from round 14 — mma.sync bf16x3, streamed K/V, fused epilogues)
// ---------------------------------------------------------------------------
#define SH  0
#define SL  16640
#define QH  33280
#define QL  34048
#define ABO 34816
#define KV  35840

__global__ __launch_bounds__(256, 2)
void attn_kernel(const float* __restrict__ attn_biases,
                 const int* __restrict__ bias_idxs)
{
    extern __shared__ bf16 smh[];
    float* ab = (float*)(smh + ABO);

    const int b  = blockIdx.z, h = blockIdx.y;
    const int bh = b * 8 + h;
    const int n0 = blockIdx.x * 32;
    const int tid = threadIdx.x;
    const int warp = tid >> 5, lane = tid & 31;
    const int r  = lane >> 2, c2 = (lane & 3) * 2;
    const int lrow = lane & 15, lcol = (lane >> 4) * 8;
    const int wb = warp & 1;
    const int wq = warp >> 1;

    const float* qb = g_q + ((size_t)b * NH_KD + h * KDIM) * N_;
    const bf16* khg = g_kp + (size_t)bh * N_ * KDIM;
    const bf16* vhg = g_vp + (size_t)bh * VDIM * N_;

    auto issue_k = [&](int t) {
        bf16* dst = smh + KV + (t & 1) * 3072;
        int e = tid;
        int plane = e >> 7, idx = e & 127;
        int row = idx >> 1, seg = (idx & 1) * 8;
        const bf16* src = (plane ? khg + PSK : khg) + (size_t)(t * 64 + row) * KDIM + seg;
        cp16(dst + plane * 1536 + row * 24 + seg, src);
        asm volatile("cp.async.commit_group;");
    };
    auto issue_v = [&](int t) {
        bf16* dst = smh + KV + (t & 1) * 9216;
#pragma unroll
        for (int i = 0; i < 4; i++) {
            int e = tid + i * 256;
            int plane = e >> 9, idx = e & 511;
            int row = idx >> 3, seg = (idx & 7) * 8;
            const bf16* src = (plane ? vhg + PSV : vhg) + (size_t)row * N_ + t * 64 + seg;
            cp16(dst + plane * 4608 + row * 72 + seg, src);
        }
        asm volatile("cp.async.commit_group;");
    };

#pragma unroll
    for (int i = 0; i < 2; i++) {
        int e = tid + i * 256;
        int k = e >> 5, n = e & 31;
        bf16 hi, lo; split2(qb[(size_t)k * N_ + n0 + n], hi, lo);
        smh[QH + n * 24 + k] = hi;
        smh[QL + n * 24 + k] = lo;
    }
    ab[tid] = attn_biases[h * N_ + tid];
    ab[tid + 256] = attn_biases[h * N_ + tid + 256];

    issue_k(0);
    __syncthreads();

    unsigned qh4[4], ql4[4];
    ldsm4(qh4, smh + QH + (wb * 16 + lrow) * 24 + lcol);
    ldsm4(ql4, smh + QL + (wb * 16 + lrow) * 24 + lcol);

#pragma unroll 1
    for (int t = 0; t < 8; t++) {
        if (t + 1 < 8) {
            issue_k(t + 1);
            asm volatile("cp.async.wait_group 1;");
        } else {
            asm volatile("cp.async.wait_group 0;");
        }
        __syncthreads();

        const bf16* kb = smh + KV + (t & 1) * 3072;
        unsigned kh4[4], kl4[4];
        ldsm4(kh4, kb + (wq * 16 + lrow) * 24 + lcol);
        ldsm4(kl4, kb + 1536 + (wq * 16 + lrow) * 24 + lcol);
#pragma unroll
        for (int sub = 0; sub < 2; sub++) {
            unsigned bh2[2]  = {kh4[sub], kh4[sub + 2]};
            unsigned bl2[2] = {kl4[sub], kl4[sub + 2]};
            float c[4] = {0.f, 0.f, 0.f, 0.f};
            mma_bf16(c, qh4, bh2);
            mma_bf16(c, ql4, bh2);
            mma_bf16(c, qh4, bl2);

            const int nr0 = wb * 16 + r, nr1 = nr0 + 8;
            const int mc = t * 64 + wq * 16 + sub * 8 + c2;
            int2 i0 = *(const int2*)&bias_idxs[(size_t)(n0 + nr0) * N_ + mc];
            int2 i1 = *(const int2*)&bias_idxs[(size_t)(n0 + nr1) * N_ + mc];
            float o0 = fmaf(c[0], 0.25f, ab[i0.x]);
            float o1 = fmaf(c[1], 0.25f, ab[i0.y]);
            float o2 = fmaf(c[2], 0.25f, ab[i1.x]);
            float o3 = fmaf(c[3], 0.25f, ab[i1.y]);
            bf16 h0, l0, h1, l1;
            split2(o0, h0, l0); split2(o1, h1, l1);
            *(unsigned*)&smh[SH + nr0 * 520 + mc] = bpack(h0, h1);
            *(unsigned*)&smh[SL + nr0 * 520 + mc] = bpack(l0, l1);
            split2(o2, h0, l0); split2(o3, h1, l1);
            *(unsigned*)&smh[SH + nr1 * 520 + mc] = bpack(h0, h1);
            *(unsigned*)&smh[SL + nr1 * 520 + mc] = bpack(l0, l1);
        }
        __syncthreads();
    }

    for (int rr = warp; rr < 32; rr += 8) {
        const int base = rr * 520;
        float e[16];
        float mx = -1e30f;
#pragma unroll
        for (int j = 0; j < 16; j++) {
            int o = base + lane + j * 32;
            e[j] = __bfloat162float(smh[SH + o]) + __bfloat162float(smh[SL + o]);
            mx = fmaxf(mx, e[j]);
        }
#pragma unroll
        for (int off = 16; off; off >>= 1)
            mx = fmaxf(mx, __shfl_xor_sync(0xffffffffu, mx, off));
        float sum = 0.f;
#pragma unroll
        for (int j = 0; j < 16; j++) { e[j] = __expf(e[j] - mx); sum += e[j]; }
#pragma unroll
        for (int off = 16; off; off >>= 1)
            sum += __shfl_xor_sync(0xffffffffu, sum, off);
        float inv = 1.f / sum;
#pragma unroll
        for (int j = 0; j < 16; j++) {
            bf16 hi, lo; split2(e[j] * inv, hi, lo);
            int o = base + lane + j * 32;
            smh[SH + o] = hi; smh[SL + o] = lo;
        }
    }

    float oacc[2][4];
#pragma unroll
    for (int i = 0; i < 2; i++)
#pragma unroll
        for (int j = 0; j < 4; j++) oacc[i][j] = 0.f;

    issue_v(0);
#pragma unroll 1
    for (int mt = 0; mt < 8; mt++) {
        if (mt + 1 < 8) {
            issue_v(mt + 1);
            asm volatile("cp.async.wait_group 1;");
        } else {
            asm volatile("cp.async.wait_group 0;");
        }
        __syncthreads();

        const bf16* vb = smh + KV + (mt & 1) * 9216;
#pragma unroll
        for (int ks = 0; ks < 4; ks++) {
            unsigned ph[4], pl[4];
            ldsm4(ph, smh + SH + (wb * 16 + lrow) * 520 + mt * 64 + ks * 16 + lcol);
            ldsm4(pl, smh + SL + (wb * 16 + lrow) * 520 + mt * 64 + ks * 16 + lcol);
            unsigned vh4[4], vl4[4];
            ldsm4(vh4, vb + (wq * 16 + lrow) * 72 + ks * 16 + lcol);
            ldsm4(vl4, vb + 4608 + (wq * 16 + lrow) * 72 + ks * 16 + lcol);
#pragma unroll
            for (int dt = 0; dt < 2; dt++) {
                unsigned bh2[2]  = {vh4[dt], vh4[dt + 2]};
                unsigned bl2[2] = {vl4[dt], vl4[dt + 2]};
                mma_bf16(oacc[dt], ph, bh2);
                mma_bf16(oacc[dt], pl, bh2);
                mma_bf16(oacc[dt], ph, bl2);
            }
        }
        __syncthreads();
    }

    bf16* aT = g_aT + (size_t)b * N_ * DH_;
#pragma unroll
    for (int dt = 0; dt < 2; dt++) {
        const int col = h * 64 + wq * 16 + dt * 8 + c2;
        const int nr0 = n0 + wb * 16 + r, nr1 = nr0 + 8;
        float v0 = fmaxf(oacc[dt][0], 0.f), v1 = fmaxf(oacc[dt][1], 0.f);
        float v2 = fmaxf(oacc[dt][2], 0.f), v3 = fmaxf(oacc[dt][3], 0.f);
        bf16 h0, l0, h1, l1;
        split2(v0, h0, l0); split2(v1, h1, l1);
        *(unsigned*)&aT[(size_t)nr0 * DH_ + col]       = bpack(h0, h1);
        *(unsigned*)&aT[PSA + (size_t)nr0 * DH_ + col] = bpack(l0, l1);
        split2(v2, h0, l0); split2(v3, h1, l1);
        *(unsigned*)&aT[(size_t)nr1 * DH_ + col]       = bpack(h0, h1);
        *(unsigned*)&aT[PSA + (size_t)nr1 * DH_ + col] = bpack(l0, l1);
    }
}

// ---------------------------------------------------------------------------
extern "C" void kernel_launch(void* const* d_in, const int* in_sizes, int n_in,
                              void* d_out, int out_size)
{
    const float* x          = (const float*)d_in[0];
    const float* qkv_w      = (const float*)d_in[1];
    const float* qkv_scale  = (const float*)d_in[2];
    const float* qkv_bias   = (const float*)d_in[3];
    const float* dw_w       = (const float*)d_in[4];
    const float* dw_scale   = (const float*)d_in[5];
    const float* dw_bias    = (const float*)d_in[6];
    const float* attn_bias  = (const float*)d_in[7];
    const float* proj_w     = (const float*)d_in[8];
    const float* proj_scale = (const float*)d_in[9];
    const float* proj_bias  = (const float*)d_in[10];
    const int*   bias_idxs  = (const int*)d_in[11];
    float* out = (float*)d_out;

    float* qkv_p;
    bf16 *wq_p, *wp_p, *xT_p, *aT_p, *vp_p, *kp_p;
    cudaGetSymbolAddress((void**)&qkv_p, g_qkv);
    cudaGetSymbolAddress((void**)&wq_p, g_wq);
    cudaGetSymbolAddress((void**)&wp_p, g_wp);
    cudaGetSymbolAddress((void**)&xT_p, g_xT);
    cudaGetSymbolAddress((void**)&aT_p, g_aT);
    cudaGetSymbolAddress((void**)&vp_p, g_vp);
    cudaGetSymbolAddress((void**)&kp_p, g_kp);

    const int gemm_smem = 81920;
    const int attn_smem = 108544;
    cudaFuncSetAttribute(gemm_mma<DIM_>,
                         cudaFuncAttributeMaxDynamicSharedMemorySize, gemm_smem);
    cudaFuncSetAttribute(gemm_mma<DH_>,
                         cudaFuncAttributeMaxDynamicSharedMemorySize, gemm_smem);
    cudaFuncSetAttribute(attn_kernel,
                         cudaFuncAttributeMaxDynamicSharedMemorySize, attn_smem);

    // 0) pack weights + transpose/pack x
    pack_kernel<<<(HQKV * DIM_ + 255) / 256, 256>>>(qkv_w, wq_p, HQKV * DIM_);
    pack_kernel<<<(DIM_ * DH_ + 255) / 256, 256>>>(proj_w, wp_p, DIM_ * DH_);
    transpose_pack<<<dim3(N_ / 32, DIM_ / 32, B_), 256>>>(
        x, xT_p, DIM_, N_, (size_t)B_ * N_ * DIM_);

    // 1) QKV GEMM: q rows -> fp32 g_qkv; k rows -> planes g_kp (fused);
    //    v rows -> planes g_vp (fused)
    gemm_mma<DIM_><<<dim3(N_ / 128, HQKV / 128, B_), 256, gemm_smem>>>(
        wq_p, xT_p, qkv_p, qkv_scale, qkv_bias, HQKV, N_,
        (size_t)HQKV * DIM_, (size_t)B_ * N_ * DIM_,
        vp_p, 2 * NH_KD, PSV, kp_p, PSK);

    // 2) depthwise 3x3x3 conv on q
    dwconv_kernel<<<(B_ * NH_KD * N_) / 256, 256>>>(dw_w, dw_scale, dw_bias);

    // 3) fused attention (2 CTAs/SM; writes relu+split aT directly)
    attn_kernel<<<dim3(N_ / 32, NHEADS, B_), 256, attn_smem>>>(attn_bias, bias_idxs);

    // 4) proj GEMM (reads aT planes)
    gemm_mma<DH_><<<dim3(N_ / 128, DIM_ / 128, B_), 256, gemm_smem>>>(
        wp_p, aT_p, out, proj_scale, proj_bias, DIM_, N_,
        (size_t)DIM_ * DH_, (size_t)B_ * N_ * DH_,
        (bf16*)nullptr, 1 << 30, 0, (bf16*)nullptr, 0);
}

// round 17
// speedup vs baseline: 2.0144x; 1.0518x over previous
#include <cuda_runtime.h>
#include <cuda_bf16.h>

#define B_      32
#define DIM_    256
#define N_      512
#define NHEADS  8
#define KDIM    16
#define NH_KD   128
#define DH_     512
#define HQKV    768
#define VDIM    64

typedef unsigned long long ull;
typedef __nv_bfloat16 bf16;

// ---------------------------------------------------------------------------
// helpers
// ---------------------------------------------------------------------------
__device__ __forceinline__ unsigned bpack(bf16 a, bf16 b) {
    __nv_bfloat162 t = __halves2bfloat162(a, b);
    return *(unsigned*)&t;
}
__device__ __forceinline__ void split2(float x, bf16& hi, bf16& lo) {
    hi = __float2bfloat16_rn(x);
    lo = __float2bfloat16_rn(x - __bfloat162float(hi));
}
__device__ __forceinline__ void mma_bf16(float* c, const unsigned* a, const unsigned* b) {
    asm volatile(
        "mma.sync.aligned.m16n8k16.row.col.f32.bf16.bf16.f32 "
        "{%0,%1,%2,%3}, {%4,%5,%6,%7}, {%8,%9}, {%0,%1,%2,%3};"
        : "+f"(c[0]), "+f"(c[1]), "+f"(c[2]), "+f"(c[3])
        : "r"(a[0]), "r"(a[1]), "r"(a[2]), "r"(a[3]), "r"(b[0]), "r"(b[1]));
}
__device__ __forceinline__ void ldsm4(unsigned* r, const bf16* p) {
    unsigned a = (unsigned)__cvta_generic_to_shared(p);
    asm volatile("ldmatrix.sync.aligned.m8n8.x4.shared.b16 {%0,%1,%2,%3}, [%4];"
                 : "=r"(r[0]), "=r"(r[1]), "=r"(r[2]), "=r"(r[3]) : "r"(a));
}
__device__ __forceinline__ void cp16(void* dst, const void* src) {
    unsigned d = (unsigned)__cvta_generic_to_shared(dst);
    asm volatile("cp.async.cg.shared.global [%0], [%1], 16;" :: "r"(d), "l"(src));
}

// ---------------------------------------------------------------------------
// Scratch (device globals; hi/lo planes stored contiguously: [2][...])
// ---------------------------------------------------------------------------
__device__ float g_qkv[(size_t)B_ * HQKV * N_];     // only q channel rows used
__device__ float g_q  [(size_t)B_ * NH_KD * N_];
__device__ bf16  g_wq [(size_t)2 * HQKV * DIM_];          // [m][k] planes
__device__ bf16  g_wp [(size_t)2 * DIM_ * DH_];
__device__ bf16  g_xT [(size_t)2 * B_ * N_ * DIM_];       // [b][n][k] planes
__device__ bf16  g_aT [(size_t)2 * B_ * N_ * DH_];        // relu(att)^T planes
__device__ bf16  g_kp [(size_t)2 * B_ * NHEADS * N_ * KDIM];   // [bh][m][k]
__device__ bf16  g_vp [(size_t)2 * B_ * NHEADS * VDIM * N_];   // [bh][d][m]

#define PSK ((size_t)B_ * NHEADS * N_ * KDIM)
#define PSV ((size_t)B_ * NHEADS * VDIM * N_)
#define PSA ((size_t)B_ * N_ * DH_)

// ---------------------------------------------------------------------------
// prep kernels
// ---------------------------------------------------------------------------
__global__ void pack_kernel(const float* __restrict__ src, bf16* __restrict__ dst, int n)
{
    int i = blockIdx.x * 256 + threadIdx.x;
    if (i < n) {
        bf16 hi, lo; split2(src[i], hi, lo);
        dst[i] = hi; dst[n + i] = lo;
    }
}

// src [b][K][N] fp32 -> dst [b][N][K] bf16 planes
__global__ void transpose_pack(const float* __restrict__ src, bf16* __restrict__ dst,
                               int K, int N, size_t ps)
{
    __shared__ float tile[32][33];
    const int b = blockIdx.z;
    const int k0 = blockIdx.y * 32, n0 = blockIdx.x * 32;
    const int tx = threadIdx.x & 31, ty = threadIdx.x >> 5;
    const float* sb = src + (size_t)b * K * N;
    bf16* db = dst + (size_t)b * N * K;
#pragma unroll
    for (int i = 0; i < 4; i++)
        tile[ty + i * 8][tx] = sb[(size_t)(k0 + ty + i * 8) * N + n0 + tx];
    __syncthreads();
#pragma unroll
    for (int i = 0; i < 4; i++) {
        float v = tile[tx][ty + i * 8];
        bf16 hi, lo; split2(v, hi, lo);
        size_t o = (size_t)(n0 + ty + i * 8) * K + k0 + tx;
        db[o] = hi; db[ps + o] = lo;
    }
}

// ---------------------------------------------------------------------------
// Tensor-core CBN GEMM (ldmatrix + cp.async), with fused epilogues:
//   m0 == NH_KD (k channels, qkv only): split planes -> kpl [bh][token][chan]
//   m0 >= vbase (v channels, qkv only): split planes -> vpl [bh][d][m]
//   otherwise: fp32 C with scale/bias
// ---------------------------------------------------------------------------
template <int K>
__global__ __launch_bounds__(256, 2)
void gemm_mma(const bf16* __restrict__ Apk, const bf16* __restrict__ Bpk,
              float* __restrict__ Cg, const float* __restrict__ scale,
              const float* __restrict__ bias, int M, int N,
              size_t aps, size_t bps,
              bf16* vpl, int vbase, size_t vps,
              bf16* kpl, size_t kps)
{
    extern __shared__ bf16 smh[];
    const int b = blockIdx.z;
    const bf16* Bb = Bpk + (size_t)b * N * K;
    float* Cb = Cg + (size_t)b * M * N;
    const int m0 = blockIdx.y * 128, n0 = blockIdx.x * 128;
    const int tid = threadIdx.x, warp = tid >> 5, lane = tid & 31;
    const int r = lane >> 2, c2 = (lane & 3) * 2;
    const int wm = warp >> 1, wn = warp & 1;
    const int lrow = lane & 15, lcol = (lane >> 4) * 8;

    float acc[2][8][4];
#pragma unroll
    for (int i = 0; i < 2; i++)
#pragma unroll
        for (int j = 0; j < 8; j++)
#pragma unroll
            for (int q = 0; q < 4; q++) acc[i][j][q] = 0.f;

    auto issue = [&](int t) {
        const int k0 = t * 32;
        bf16* sb = smh + (t & 1) * 20480;
#pragma unroll
        for (int i = 0; i < 8; i++) {
            int e = tid + i * 256;
            int plane = e >> 9, idx = e & 511;
            int row = idx >> 2, seg = (idx & 3) * 8;
            const bf16* src;
            bf16* dst;
            if (plane == 0)      { src = Apk + (size_t)(m0 + row) * K + k0 + seg;       dst = sb + row * 40 + seg; }
            else if (plane == 1) { src = Apk + aps + (size_t)(m0 + row) * K + k0 + seg; dst = sb + 5120 + row * 40 + seg; }
            else if (plane == 2) { src = Bb + (size_t)(n0 + row) * K + k0 + seg;        dst = sb + 10240 + row * 40 + seg; }
            else                 { src = Bb + bps + (size_t)(n0 + row) * K + k0 + seg;  dst = sb + 15360 + row * 40 + seg; }
            cp16(dst, src);
        }
        asm volatile("cp.async.commit_group;");
    };

    issue(0);
    constexpr int T = K / 32;
#pragma unroll 1
    for (int t = 0; t < T; t++) {
        if (t + 1 < T) {
            issue(t + 1);
            asm volatile("cp.async.wait_group 1;");
        } else {
            asm volatile("cp.async.wait_group 0;");
        }
        __syncthreads();

        const bf16* As = smh + (t & 1) * 20480;
        const bf16* Bs = As + 10240;
#pragma unroll
        for (int ks = 0; ks < 32; ks += 16) {
            unsigned ah[2][4], al[2][4];
#pragma unroll
            for (int mt = 0; mt < 2; mt++) {
                const int row = wm * 32 + mt * 16 + lrow;
                ldsm4(ah[mt], As + row * 40 + ks + lcol);
                ldsm4(al[mt], As + 5120 + row * 40 + ks + lcol);
            }
#pragma unroll
            for (int ng = 0; ng < 4; ng++) {
                const int row = wn * 64 + ng * 16 + lrow;
                unsigned h4[4], l4[4];
                ldsm4(h4, Bs + row * 40 + ks + lcol);
                ldsm4(l4, Bs + 5120 + row * 40 + ks + lcol);
#pragma unroll
                for (int sub = 0; sub < 2; sub++) {
                    unsigned bh[2]  = {h4[sub], h4[sub + 2]};
                    unsigned bl2[2] = {l4[sub], l4[sub + 2]};
                    const int nt = ng * 2 + sub;
#pragma unroll
                    for (int mt = 0; mt < 2; mt++) {
                        mma_bf16(acc[mt][nt], ah[mt], bh);
                        mma_bf16(acc[mt][nt], al[mt], bh);
                        mma_bf16(acc[mt][nt], ah[mt], bl2);
                    }
                }
            }
        }
        __syncthreads();
    }

    if (kpl != nullptr && m0 == NH_KD) {
        // fused k-channel epilogue: scale/bias -> split planes, [bh][token][chan]
#pragma unroll
        for (int mt = 0; mt < 2; mt++) {
            const int mr0 = m0 + wm * 32 + mt * 16 + r;
            const int mr1 = mr0 + 8;
            const float s0 = scale[mr0], b0 = bias[mr0];
            const float s1 = scale[mr1], b1 = bias[mr1];
            const int c0 = mr0 - NH_KD, c1 = mr1 - NH_KD;
            bf16* kb0 = kpl + ((size_t)(b * 8 + (c0 >> 4)) * N_) * KDIM + (c0 & 15);
            bf16* kb1 = kpl + ((size_t)(b * 8 + (c1 >> 4)) * N_) * KDIM + (c1 & 15);
#pragma unroll
            for (int nt = 0; nt < 8; nt++) {
                const int col = n0 + wn * 64 + nt * 8 + c2;
                float v0 = fmaf(acc[mt][nt][0], s0, b0);
                float v1 = fmaf(acc[mt][nt][1], s0, b0);
                float v2 = fmaf(acc[mt][nt][2], s1, b1);
                float v3 = fmaf(acc[mt][nt][3], s1, b1);
                bf16 h0, l0, h1, l1;
                split2(v0, h0, l0); split2(v1, h1, l1);
                kb0[(size_t)col * KDIM]            = h0;
                kb0[(size_t)(col + 1) * KDIM]      = h1;
                kb0[kps + (size_t)col * KDIM]       = l0;
                kb0[kps + (size_t)(col + 1) * KDIM] = l1;
                split2(v2, h0, l0); split2(v3, h1, l1);
                kb1[(size_t)col * KDIM]            = h0;
                kb1[(size_t)(col + 1) * KDIM]      = h1;
                kb1[kps + (size_t)col * KDIM]       = l0;
                kb1[kps + (size_t)(col + 1) * KDIM] = l1;
            }
        }
    } else if (vpl != nullptr && m0 >= vbase) {
        // fused v-channel epilogue: scale/bias -> split planes, [bh][d][m]
#pragma unroll
        for (int mt = 0; mt < 2; mt++) {
            const int mr0 = m0 + wm * 32 + mt * 16 + r;
            const int mr1 = mr0 + 8;
            const float s0 = scale[mr0], b0 = bias[mr0];
            const float s1 = scale[mr1], b1 = bias[mr1];
            const int vo0 = mr0 - vbase, vo1 = mr1 - vbase;
            bf16* d0 = vpl + ((size_t)(b * 8 + (vo0 >> 6)) * VDIM + (vo0 & 63)) * N_;
            bf16* d1 = vpl + ((size_t)(b * 8 + (vo1 >> 6)) * VDIM + (vo1 & 63)) * N_;
#pragma unroll
            for (int nt = 0; nt < 8; nt++) {
                const int col = n0 + wn * 64 + nt * 8 + c2;
                float v0 = fmaf(acc[mt][nt][0], s0, b0);
                float v1 = fmaf(acc[mt][nt][1], s0, b0);
                float v2 = fmaf(acc[mt][nt][2], s1, b1);
                float v3 = fmaf(acc[mt][nt][3], s1, b1);
                bf16 h0, l0, h1, l1;
                split2(v0, h0, l0); split2(v1, h1, l1);
                *(unsigned*)&d0[col]       = bpack(h0, h1);
                *(unsigned*)&d0[vps + col] = bpack(l0, l1);
                split2(v2, h0, l0); split2(v3, h1, l1);
                *(unsigned*)&d1[col]       = bpack(h0, h1);
                *(unsigned*)&d1[vps + col] = bpack(l0, l1);
            }
        }
    } else {
#pragma unroll
        for (int mt = 0; mt < 2; mt++) {
            const int mr0 = m0 + wm * 32 + mt * 16 + r;
            const int mr1 = mr0 + 8;
            const float s0 = scale[mr0], b0 = bias[mr0];
            const float s1 = scale[mr1], b1 = bias[mr1];
#pragma unroll
            for (int nt = 0; nt < 8; nt++) {
                const int col = n0 + wn * 64 + nt * 8 + c2;
                float2 o0, o1;
                o0.x = fmaf(acc[mt][nt][0], s0, b0);
                o0.y = fmaf(acc[mt][nt][1], s0, b0);
                o1.x = fmaf(acc[mt][nt][2], s1, b1);
                o1.y = fmaf(acc[mt][nt][3], s1, b1);
                *(float2*)&Cb[(size_t)mr0 * N + col] = o0;
                *(float2*)&Cb[(size_t)mr1 * N + col] = o1;
            }
        }
    }
}

// ---------------------------------------------------------------------------
// Depthwise 3x3x3 conv on q channels, pad=1, then scale/bias.
// ---------------------------------------------------------------------------
__global__ __launch_bounds__(256)
void dwconv_kernel(const float* __restrict__ w,
                   const float* __restrict__ scale,
                   const float* __restrict__ bias)
{
    int idx = blockIdx.x * 256 + threadIdx.x;
    int n = idx & 511;
    int c = (idx >> 9) & 127;
    int b = idx >> 16;
    int xx = n & 7, yy = (n >> 3) & 7, zz = n >> 6;

    const float* src = g_qkv + ((size_t)b * HQKV + c) * N_;
    const float* wc = w + c * 27;
    float acc = 0.f;
#pragma unroll
    for (int dz = 0; dz < 3; dz++) {
        int z = zz + dz - 1;
        if (z < 0 || z > 7) continue;
#pragma unroll
        for (int dy = 0; dy < 3; dy++) {
            int y = yy + dy - 1;
            if (y < 0 || y > 7) continue;
#pragma unroll
            for (int dx = 0; dx < 3; dx++) {
                int x = xx + dx - 1;
                if (x < 0 || x > 7) continue;
                acc = fmaf(src[z * 64 + y * 8 + x], wc[dz * 9 + dy * 3 + dx], acc);
            }
        }
    }
    g_q[((size_t)b * NH_KD + c) * N_ + n] = fmaf(acc, scale[c], bias[c]);
}

// ---------------------------------------------------------------------------
// Fused attention per (b, h, 32-row n-tile), 256 threads (8 warps), 2 CTA/SM.
// K fully SMEM-resident (interleaved hi/lo, [512][40] pitch: hi @+0, lo @+16)
// -> phase 1 runs with ZERO barriers. V double-buffered in the K region for
// phase 3 (issue_v(0) hoisted before softmax for overlap).
// SMEM (halves): Shi@0 [32][520], Slo@16640, qhi@33280 [32][24], qlo@34048,
// ab fp32[512]@34816, K/V scratch @35840: K [512][40]=20480 halves
// (V bufs 2x9216 reuse this region). Total 56320 halves = 112640 B.
// ---------------------------------------------------------------------------
#define SH  0
#define SL  16640
#define QH  33280
#define QL  34048
#define ABO 34816
#define KV  35840

__global__ __launch_bounds__(256, 2)
void attn_kernel(const float* __restrict__ attn_biases,
                 const int* __restrict__ bias_idxs)
{
    extern __shared__ bf16 smh[];
    float* ab = (float*)(smh + ABO);

    const int b  = blockIdx.z, h = blockIdx.y;
    const int bh = b * 8 + h;
    const int n0 = blockIdx.x * 32;
    const int tid = threadIdx.x;
    const int warp = tid >> 5, lane = tid & 31;
    const int r  = lane >> 2, c2 = (lane & 3) * 2;
    const int lrow = lane & 15, lcol = (lane >> 4) * 8;
    const int wb = warp & 1;
    const int wq = warp >> 1;

    const float* qb = g_q + ((size_t)b * NH_KD + h * KDIM) * N_;
    const bf16* khg = g_kp + (size_t)bh * N_ * KDIM;
    const bf16* vhg = g_vp + (size_t)bh * VDIM * N_;

    auto issue_v = [&](int t) {
        bf16* dst = smh + KV + (t & 1) * 9216;
#pragma unroll
        for (int i = 0; i < 4; i++) {
            int e = tid + i * 256;
            int plane = e >> 9, idx = e & 511;
            int row = idx >> 3, seg = (idx & 7) * 8;
            const bf16* src = (plane ? vhg + PSV : vhg) + (size_t)row * N_ + t * 64 + seg;
            cp16(dst + plane * 4608 + row * 72 + seg, src);
        }
        asm volatile("cp.async.commit_group;");
    };

    // stage ALL of K: interleaved hi/lo, [512][40] (hi @+0, lo @+16)
#pragma unroll
    for (int i = 0; i < 8; i++) {
        int e = tid + i * 256;
        int plane = e >> 10, idx = e & 1023;
        int row = idx >> 1, seg = (idx & 1) * 8;
        const bf16* src = (plane ? khg + PSK : khg) + (size_t)row * KDIM + seg;
        cp16(smh + KV + row * 40 + plane * 16 + seg, src);
    }
    asm volatile("cp.async.commit_group;");

    // stage q split [32 n][16 k] (512 elems, 2 per thread)
#pragma unroll
    for (int i = 0; i < 2; i++) {
        int e = tid + i * 256;
        int k = e >> 5, n = e & 31;
        bf16 hi, lo; split2(qb[(size_t)k * N_ + n0 + n], hi, lo);
        smh[QH + n * 24 + k] = hi;
        smh[QL + n * 24 + k] = lo;
    }
    ab[tid] = attn_biases[h * N_ + tid];
    ab[tid + 256] = attn_biases[h * N_ + tid + 256];

    asm volatile("cp.async.wait_group 0;");
    __syncthreads();

    // q fragment (held across phase 1)
    unsigned qh4[4], ql4[4];
    ldsm4(qh4, smh + QH + (wb * 16 + lrow) * 24 + lcol);
    ldsm4(ql4, smh + QL + (wb * 16 + lrow) * 24 + lcol);

    // ---- Phase 1: S = q^T k * 0.25 + bias over 8 m-tiles of 64, NO barriers ----
#pragma unroll 2
    for (int t = 0; t < 8; t++) {
        const bf16* kb = smh + KV + (size_t)(t * 64 + wq * 16 + lrow) * 40 + lcol;
        unsigned kh4[4], kl4[4];
        ldsm4(kh4, kb);
        ldsm4(kl4, kb + 16);
#pragma unroll
        for (int sub = 0; sub < 2; sub++) {
            unsigned bh2[2]  = {kh4[sub], kh4[sub + 2]};
            unsigned bl2[2] = {kl4[sub], kl4[sub + 2]};
            float c[4] = {0.f, 0.f, 0.f, 0.f};
            mma_bf16(c, qh4, bh2);
            mma_bf16(c, ql4, bh2);
            mma_bf16(c, qh4, bl2);

            const int nr0 = wb * 16 + r, nr1 = nr0 + 8;
            const int mc = t * 64 + wq * 16 + sub * 8 + c2;
            int2 i0 = *(const int2*)&bias_idxs[(size_t)(n0 + nr0) * N_ + mc];
            int2 i1 = *(const int2*)&bias_idxs[(size_t)(n0 + nr1) * N_ + mc];
            float o0 = fmaf(c[0], 0.25f, ab[i0.x]);
            float o1 = fmaf(c[1], 0.25f, ab[i0.y]);
            float o2 = fmaf(c[2], 0.25f, ab[i1.x]);
            float o3 = fmaf(c[3], 0.25f, ab[i1.y]);
            bf16 h0, l0, h1, l1;
            split2(o0, h0, l0); split2(o1, h1, l1);
            *(unsigned*)&smh[SH + nr0 * 520 + mc] = bpack(h0, h1);
            *(unsigned*)&smh[SL + nr0 * 520 + mc] = bpack(l0, l1);
            split2(o2, h0, l0); split2(o3, h1, l1);
            *(unsigned*)&smh[SH + nr1 * 520 + mc] = bpack(h0, h1);
            *(unsigned*)&smh[SL + nr1 * 520 + mc] = bpack(l0, l1);
        }
    }
    __syncthreads();   // S complete; all K reads done (K region now reusable)

    // V tile 0 loads overlap with softmax
    issue_v(0);

    // ---- Phase 2: softmax (4 rows per warp) ----
    for (int rr = warp; rr < 32; rr += 8) {
        const int base = rr * 520;
        float e[16];
        float mx = -1e30f;
#pragma unroll
        for (int j = 0; j < 16; j++) {
            int o = base + lane + j * 32;
            e[j] = __bfloat162float(smh[SH + o]) + __bfloat162float(smh[SL + o]);
            mx = fmaxf(mx, e[j]);
        }
#pragma unroll
        for (int off = 16; off; off >>= 1)
            mx = fmaxf(mx, __shfl_xor_sync(0xffffffffu, mx, off));
        float sum = 0.f;
#pragma unroll
        for (int j = 0; j < 16; j++) { e[j] = __expf(e[j] - mx); sum += e[j]; }
#pragma unroll
        for (int off = 16; off; off >>= 1)
            sum += __shfl_xor_sync(0xffffffffu, sum, off);
        float inv = 1.f / sum;
#pragma unroll
        for (int j = 0; j < 16; j++) {
            bf16 hi, lo; split2(e[j] * inv, hi, lo);
            int o = base + lane + j * 32;
            smh[SH + o] = hi; smh[SL + o] = lo;
        }
    }

    // ---- Phase 3: O[n][d] = P @ V^T over 8 m-tiles of 64 ----
    float oacc[2][4];
#pragma unroll
    for (int i = 0; i < 2; i++)
#pragma unroll
        for (int j = 0; j < 4; j++) oacc[i][j] = 0.f;

#pragma unroll 1
    for (int mt = 0; mt < 8; mt++) {
        if (mt + 1 < 8) {
            issue_v(mt + 1);
            asm volatile("cp.async.wait_group 1;");
        } else {
            asm volatile("cp.async.wait_group 0;");
        }
        __syncthreads();   // V tile ready; P writes visible (first iteration)

        const bf16* vb = smh + KV + (mt & 1) * 9216;
#pragma unroll
        for (int ks = 0; ks < 4; ks++) {
            unsigned ph[4], pl[4];
            ldsm4(ph, smh + SH + (wb * 16 + lrow) * 520 + mt * 64 + ks * 16 + lcol);
            ldsm4(pl, smh + SL + (wb * 16 + lrow) * 520 + mt * 64 + ks * 16 + lcol);
            unsigned vh4[4], vl4[4];
            ldsm4(vh4, vb + (wq * 16 + lrow) * 72 + ks * 16 + lcol);
            ldsm4(vl4, vb + 4608 + (wq * 16 + lrow) * 72 + ks * 16 + lcol);
#pragma unroll
            for (int dt = 0; dt < 2; dt++) {
                unsigned bh2[2]  = {vh4[dt], vh4[dt + 2]};
                unsigned bl2[2] = {vl4[dt], vl4[dt + 2]};
                mma_bf16(oacc[dt], ph, bh2);
                mma_bf16(oacc[dt], pl, bh2);
                mma_bf16(oacc[dt], ph, bl2);
            }
        }
        __syncthreads();
    }

    // ---- epilogue: relu + split + store directly to g_aT [b][n][dh] planes ----
    bf16* aT = g_aT + (size_t)b * N_ * DH_;
#pragma unroll
    for (int dt = 0; dt < 2; dt++) {
        const int col = h * 64 + wq * 16 + dt * 8 + c2;
        const int nr0 = n0 + wb * 16 + r, nr1 = nr0 + 8;
        float v0 = fmaxf(oacc[dt][0], 0.f), v1 = fmaxf(oacc[dt][1], 0.f);
        float v2 = fmaxf(oacc[dt][2], 0.f), v3 = fmaxf(oacc[dt][3], 0.f);
        bf16 h0, l0, h1, l1;
        split2(v0, h0, l0); split2(v1, h1, l1);
        *(unsigned*)&aT[(size_t)nr0 * DH_ + col]       = bpack(h0, h1);
        *(unsigned*)&aT[PSA + (size_t)nr0 * DH_ + col] = bpack(l0, l1);
        split2(v2, h0, l0); split2(v3, h1, l1);
        *(unsigned*)&aT[(size_t)nr1 * DH_ + col]       = bpack(h0, h1);
        *(unsigned*)&aT[PSA + (size_t)nr1 * DH_ + col] = bpack(l0, l1);
    }
}

// ---------------------------------------------------------------------------
extern "C" void kernel_launch(void* const* d_in, const int* in_sizes, int n_in,
                              void* d_out, int out_size)
{
    const float* x          = (const float*)d_in[0];
    const float* qkv_w      = (const float*)d_in[1];
    const float* qkv_scale  = (const float*)d_in[2];
    const float* qkv_bias   = (const float*)d_in[3];
    const float* dw_w       = (const float*)d_in[4];
    const float* dw_scale   = (const float*)d_in[5];
    const float* dw_bias    = (const float*)d_in[6];
    const float* attn_bias  = (const float*)d_in[7];
    const float* proj_w     = (const float*)d_in[8];
    const float* proj_scale = (const float*)d_in[9];
    const float* proj_bias  = (const float*)d_in[10];
    const int*   bias_idxs  = (const int*)d_in[11];
    float* out = (float*)d_out;

    float* qkv_p;
    bf16 *wq_p, *wp_p, *xT_p, *aT_p, *vp_p, *kp_p;
    cudaGetSymbolAddress((void**)&qkv_p, g_qkv);
    cudaGetSymbolAddress((void**)&wq_p, g_wq);
    cudaGetSymbolAddress((void**)&wp_p, g_wp);
    cudaGetSymbolAddress((void**)&xT_p, g_xT);
    cudaGetSymbolAddress((void**)&aT_p, g_aT);
    cudaGetSymbolAddress((void**)&vp_p, g_vp);
    cudaGetSymbolAddress((void**)&kp_p, g_kp);

    const int gemm_smem = 81920;
    const int attn_smem = 112640;
    cudaFuncSetAttribute(gemm_mma<DIM_>,
                         cudaFuncAttributeMaxDynamicSharedMemorySize, gemm_smem);
    cudaFuncSetAttribute(gemm_mma<DH_>,
                         cudaFuncAttributeMaxDynamicSharedMemorySize, gemm_smem);
    cudaFuncSetAttribute(attn_kernel,
                         cudaFuncAttributeMaxDynamicSharedMemorySize, attn_smem);

    // 0) pack weights + transpose/pack x
    pack_kernel<<<(HQKV * DIM_ + 255) / 256, 256>>>(qkv_w, wq_p, HQKV * DIM_);
    pack_kernel<<<(DIM_ * DH_ + 255) / 256, 256>>>(proj_w, wp_p, DIM_ * DH_);
    transpose_pack<<<dim3(N_ / 32, DIM_ / 32, B_), 256>>>(
        x, xT_p, DIM_, N_, (size_t)B_ * N_ * DIM_);

    // 1) QKV GEMM: q rows -> fp32 g_qkv; k rows -> planes g_kp (fused);
    //    v rows -> planes g_vp (fused)
    gemm_mma<DIM_><<<dim3(N_ / 128, HQKV / 128, B_), 256, gemm_smem>>>(
        wq_p, xT_p, qkv_p, qkv_scale, qkv_bias, HQKV, N_,
        (size_t)HQKV * DIM_, (size_t)B_ * N_ * DIM_,
        vp_p, 2 * NH_KD, PSV, kp_p, PSK);

    // 2) depthwise 3x3x3 conv on q
    dwconv_kernel<<<(B_ * NH_KD * N_) / 256, 256>>>(dw_w, dw_scale, dw_bias);

    // 3) fused attention (2 CTAs/SM; K resident, zero-barrier phase 1)
    attn_kernel<<<dim3(N_ / 32, NHEADS, B_), 256, attn_smem>>>(attn_bias, bias_idxs);

    // 4) proj GEMM (reads aT planes)
    gemm_mma<DH_><<<dim3(N_ / 128, DIM_ / 128, B_), 256, gemm_smem>>>(
        wp_p, aT_p, out, proj_scale, proj_bias, DIM_, N_,
        (size_t)DIM_ * DH_, (size_t)B_ * N_ * DH_,
        (bf16*)nullptr, 1 << 30, 0, (bf16*)nullptr, 0);
}